// round 1
// baseline (speedup 1.0000x reference)
#include <cuda_runtime.h>
#include <math_constants.h>

#define BDIM   4
#define SLEN   2048
#define DMODEL 512
#define HNUM   8
#define KDIM   64
#define BSROWS (BDIM * SLEN)   // 8192

// ---------------- scratch (static device globals; no allocation) ----------------
__device__ float g_q[BDIM * HNUM * SLEN * KDIM];   // [b][h][s][k]
__device__ float g_k[BDIM * HNUM * SLEN * KDIM];
__device__ float g_v[BDIM * HNUM * SLEN * KDIM];
__device__ float g_c[BSROWS * DMODEL];             // concat [b][s][h*K+k]

// =====================================================================
// Kernel 1: QKV projection.
// grid = (BSROWS/64, 3*HNUM), block = 256.
// Block (mx, hj) computes rows mx*64..+63 of x against weight slab hj
// (512 x 64) and scatters into g_q/g_k/g_v in [b][h][s][k] layout.
// =====================================================================
__global__ __launch_bounds__(256) void qkv_kernel(const float* __restrict__ x,
                                                  const float* __restrict__ w)
{
    __shared__ float As[16][65];   // [d][row], pad 65
    __shared__ float Bs[16][64];   // [d][col]

    const int hj   = blockIdx.y;
    const int row0 = blockIdx.x * 64;
    const float* wslab = w + (size_t)hj * (DMODEL * KDIM);

    const int tid = threadIdx.x;
    const int ty  = tid >> 4;       // 0..15 -> rows ty*4..+3
    const int tx  = tid & 15;       // 0..15 -> cols tx*4..+3
    const int ty4 = ty * 4, tx4 = tx * 4;

    float acc[4][4];
#pragma unroll
    for (int i = 0; i < 4; i++)
#pragma unroll
        for (int j = 0; j < 4; j++) acc[i][j] = 0.f;

    for (int d0 = 0; d0 < DMODEL; d0 += 16) {
#pragma unroll
        for (int t = 0; t < 4; t++) {
            int idx = tid + t * 256;          // 1024 elems: 64 rows x 16 d
            int r = idx >> 4, d = idx & 15;
            As[d][r] = x[(size_t)(row0 + r) * DMODEL + d0 + d];
        }
#pragma unroll
        for (int t = 0; t < 4; t++) {
            int idx = tid + t * 256;          // 16 d x 64 cols
            int d = idx >> 6, c = idx & 63;
            Bs[d][c] = wslab[(size_t)(d0 + d) * KDIM + c];
        }
        __syncthreads();

#pragma unroll
        for (int d = 0; d < 16; d++) {
            float a0 = As[d][ty4 + 0];
            float a1 = As[d][ty4 + 1];
            float a2 = As[d][ty4 + 2];
            float a3 = As[d][ty4 + 3];
            float4 b = *(const float4*)&Bs[d][tx4];
            acc[0][0] += a0 * b.x; acc[0][1] += a0 * b.y; acc[0][2] += a0 * b.z; acc[0][3] += a0 * b.w;
            acc[1][0] += a1 * b.x; acc[1][1] += a1 * b.y; acc[1][2] += a1 * b.z; acc[1][3] += a1 * b.w;
            acc[2][0] += a2 * b.x; acc[2][1] += a2 * b.y; acc[2][2] += a2 * b.z; acc[2][3] += a2 * b.w;
            acc[3][0] += a3 * b.x; acc[3][1] += a3 * b.y; acc[3][2] += a3 * b.z; acc[3][3] += a3 * b.w;
        }
        __syncthreads();
    }

    const int h  = hj / 3;
    const int j3 = hj % 3;
    float* dst = (j3 == 0) ? g_q : (j3 == 1) ? g_k : g_v;

#pragma unroll
    for (int i = 0; i < 4; i++) {
        int row = row0 + ty4 + i;
        int b   = row >> 11;            // /2048
        int s   = row & (SLEN - 1);
        size_t base = ((size_t)(b * HNUM + h) * SLEN + s) * KDIM + tx4;
        float4 v = make_float4(acc[i][0], acc[i][1], acc[i][2], acc[i][3]);
        *(float4*)&dst[base] = v;
    }
}

// =====================================================================
// Kernel 2: flash attention, one CTA per (bh, 64-query tile).
// grid = (SLEN/64, BDIM*HNUM), block = 256, 68KB dynamic smem.
// =====================================================================
#define PADQ 68   // float stride; 68*4B keeps float4 alignment for d-major tiles

__global__ __launch_bounds__(256) void attn_kernel()
{
    extern __shared__ float sm[];
    float* Qs = sm;                  // [d][row]  64 x PADQ  (pre-scaled by 1/8)
    float* Ks = Qs + 64 * PADQ;      // [d][key]  64 x PADQ
    float* Vs = Ks + 64 * PADQ;      // [t][col]  64 x PADQ
    float* Ps = Vs + 64 * PADQ;      // [row][t]  64 x PADQ

    const int bh = blockIdx.y;
    const int q0 = blockIdx.x * 64;

    const float* qp = g_q + ((size_t)bh * SLEN + q0) * KDIM;
    const float* kp = g_k + (size_t)bh * SLEN * KDIM;
    const float* vp = g_v + (size_t)bh * SLEN * KDIM;

    const int tid = threadIdx.x;
    const int ty  = tid >> 4, tx = tid & 15;
    const int ty4 = ty * 4, tx4 = tx * 4;

    // Load Q (transposed to d-major), scaled by 1/sqrt(64)
#pragma unroll
    for (int t = 0; t < 16; t++) {
        int idx = tid + t * 256;      // 4096 elems
        int r = idx >> 6, d = idx & 63;
        Qs[d * PADQ + r] = qp[(size_t)r * KDIM + d] * 0.125f;
    }

    float m_[4], l_[4], o[4][4];
#pragma unroll
    for (int i = 0; i < 4; i++) {
        m_[i] = -CUDART_INF_F;
        l_[i] = 0.f;
#pragma unroll
        for (int j = 0; j < 4; j++) o[i][j] = 0.f;
    }
    __syncthreads();

    for (int t0 = 0; t0 < SLEN; t0 += 64) {
        // load K tile (d-major) and V tile (t-major)
#pragma unroll
        for (int t = 0; t < 16; t++) {
            int idx = tid + t * 256;
            int r = idx >> 6, d = idx & 63;
            Ks[d * PADQ + r] = kp[(size_t)(t0 + r) * KDIM + d];
        }
#pragma unroll
        for (int t = 0; t < 16; t++) {
            int idx = tid + t * 256;
            int r = idx >> 6, c = idx & 63;
            Vs[r * PADQ + c] = vp[(size_t)(t0 + r) * KDIM + c];
        }
        __syncthreads();

        // S = Qs^T Ks  (64q x 64k), microtile 4x4
        float s[4][4];
#pragma unroll
        for (int i = 0; i < 4; i++)
#pragma unroll
            for (int j = 0; j < 4; j++) s[i][j] = 0.f;

#pragma unroll 8
        for (int d = 0; d < 64; d++) {
            float a0 = Qs[d * PADQ + ty4 + 0];
            float a1 = Qs[d * PADQ + ty4 + 1];
            float a2 = Qs[d * PADQ + ty4 + 2];
            float a3 = Qs[d * PADQ + ty4 + 3];
            float4 b = *(const float4*)&Ks[d * PADQ + tx4];
            s[0][0] += a0 * b.x; s[0][1] += a0 * b.y; s[0][2] += a0 * b.z; s[0][3] += a0 * b.w;
            s[1][0] += a1 * b.x; s[1][1] += a1 * b.y; s[1][2] += a1 * b.z; s[1][3] += a1 * b.w;
            s[2][0] += a2 * b.x; s[2][1] += a2 * b.y; s[2][2] += a2 * b.z; s[2][3] += a2 * b.w;
            s[3][0] += a3 * b.x; s[3][1] += a3 * b.y; s[3][2] += a3 * b.z; s[3][3] += a3 * b.w;
        }

        // online softmax per row; row owned by the 16 lanes sharing ty
#pragma unroll
        for (int i = 0; i < 4; i++) {
            float tm = fmaxf(fmaxf(s[i][0], s[i][1]), fmaxf(s[i][2], s[i][3]));
#pragma unroll
            for (int off = 8; off >= 1; off >>= 1)
                tm = fmaxf(tm, __shfl_xor_sync(0xffffffffu, tm, off));
            float mn = fmaxf(m_[i], tm);
            float alpha = __expf(m_[i] - mn);
            float ts = 0.f;
#pragma unroll
            for (int j = 0; j < 4; j++) {
                s[i][j] = __expf(s[i][j] - mn);
                ts += s[i][j];
            }
#pragma unroll
            for (int off = 8; off >= 1; off >>= 1)
                ts += __shfl_xor_sync(0xffffffffu, ts, off);
            l_[i] = l_[i] * alpha + ts;
            m_[i] = mn;
#pragma unroll
            for (int j = 0; j < 4; j++) o[i][j] *= alpha;
            *(float4*)&Ps[(ty4 + i) * PADQ + tx4] =
                make_float4(s[i][0], s[i][1], s[i][2], s[i][3]);
        }
        __syncthreads();

        // O += P @ V
#pragma unroll 8
        for (int t = 0; t < 64; t++) {
            float a0 = Ps[(ty4 + 0) * PADQ + t];
            float a1 = Ps[(ty4 + 1) * PADQ + t];
            float a2 = Ps[(ty4 + 2) * PADQ + t];
            float a3 = Ps[(ty4 + 3) * PADQ + t];
            float4 v4 = *(const float4*)&Vs[t * PADQ + tx4];
            o[0][0] += a0 * v4.x; o[0][1] += a0 * v4.y; o[0][2] += a0 * v4.z; o[0][3] += a0 * v4.w;
            o[1][0] += a1 * v4.x; o[1][1] += a1 * v4.y; o[1][2] += a1 * v4.z; o[1][3] += a1 * v4.w;
            o[2][0] += a2 * v4.x; o[2][1] += a2 * v4.y; o[2][2] += a2 * v4.z; o[2][3] += a2 * v4.w;
            o[3][0] += a3 * v4.x; o[3][1] += a3 * v4.y; o[3][2] += a3 * v4.z; o[3][3] += a3 * v4.w;
        }
        __syncthreads();
    }

    // writeout into concat layout [b][s][h*K + k]
    const int b = bh >> 3, h = bh & 7;
#pragma unroll
    for (int i = 0; i < 4; i++) {
        float inv = 1.f / l_[i];
        int srow = q0 + ty4 + i;
        size_t base = ((size_t)b * SLEN + srow) * DMODEL + h * KDIM + tx4;
        *(float4*)&g_c[base] =
            make_float4(o[i][0] * inv, o[i][1] * inv, o[i][2] * inv, o[i][3] * inv);
    }
}

// =====================================================================
// Kernel 3: output projection. concat (8192x512) @ head_kernel (512x512)
// grid = (BSROWS/64, DMODEL/64), block = 256.
// =====================================================================
__global__ __launch_bounds__(256) void outproj_kernel(const float* __restrict__ hk,
                                                      float* __restrict__ out)
{
    __shared__ float As[16][65];
    __shared__ float Bs[16][64];

    const int n0   = blockIdx.y * 64;
    const int row0 = blockIdx.x * 64;

    const int tid = threadIdx.x;
    const int ty  = tid >> 4, tx = tid & 15;
    const int ty4 = ty * 4, tx4 = tx * 4;

    float acc[4][4];
#pragma unroll
    for (int i = 0; i < 4; i++)
#pragma unroll
        for (int j = 0; j < 4; j++) acc[i][j] = 0.f;

    for (int e0 = 0; e0 < DMODEL; e0 += 16) {
#pragma unroll
        for (int t = 0; t < 4; t++) {
            int idx = tid + t * 256;
            int r = idx >> 4, d = idx & 15;
            As[d][r] = g_c[(size_t)(row0 + r) * DMODEL + e0 + d];
        }
#pragma unroll
        for (int t = 0; t < 4; t++) {
            int idx = tid + t * 256;
            int d = idx >> 6, c = idx & 63;
            Bs[d][c] = hk[(size_t)(e0 + d) * DMODEL + n0 + c];
        }
        __syncthreads();

#pragma unroll
        for (int d = 0; d < 16; d++) {
            float a0 = As[d][ty4 + 0];
            float a1 = As[d][ty4 + 1];
            float a2 = As[d][ty4 + 2];
            float a3 = As[d][ty4 + 3];
            float4 b = *(const float4*)&Bs[d][tx4];
            acc[0][0] += a0 * b.x; acc[0][1] += a0 * b.y; acc[0][2] += a0 * b.z; acc[0][3] += a0 * b.w;
            acc[1][0] += a1 * b.x; acc[1][1] += a1 * b.y; acc[1][2] += a1 * b.z; acc[1][3] += a1 * b.w;
            acc[2][0] += a2 * b.x; acc[2][1] += a2 * b.y; acc[2][2] += a2 * b.z; acc[2][3] += a2 * b.w;
            acc[3][0] += a3 * b.x; acc[3][1] += a3 * b.y; acc[3][2] += a3 * b.z; acc[3][3] += a3 * b.w;
        }
        __syncthreads();
    }

#pragma unroll
    for (int i = 0; i < 4; i++) {
        size_t base = (size_t)(row0 + ty4 + i) * DMODEL + n0 + tx4;
        *(float4*)&out[base] = make_float4(acc[i][0], acc[i][1], acc[i][2], acc[i][3]);
    }
}

// =====================================================================
extern "C" void kernel_launch(void* const* d_in, const int* in_sizes, int n_in,
                              void* d_out, int out_size)
{
    const float* x    = (const float*)d_in[0];   // (4, 2048, 512)
    const float* kern = (const float*)d_in[1];   // (24, 512, 64)
    const float* hk   = (const float*)d_in[2];   // (512, 512)
    float* out = (float*)d_out;                  // (4, 2048, 512)

    const int smem_attn = 4 * 64 * PADQ * (int)sizeof(float);  // 69632 B
    cudaFuncSetAttribute(attn_kernel,
                         cudaFuncAttributeMaxDynamicSharedMemorySize, smem_attn);

    qkv_kernel<<<dim3(BSROWS / 64, 3 * HNUM), 256>>>(x, kern);
    attn_kernel<<<dim3(SLEN / 64, BDIM * HNUM), 256, smem_attn>>>();
    outproj_kernel<<<dim3(BSROWS / 64, DMODEL / 64), 256>>>(hk, out);
}

// round 4
// speedup vs baseline: 2.0970x; 2.0970x over previous
#include <cuda_runtime.h>
#include <cuda_bf16.h>

#define BDIM   4
#define SLEN   2048
#define DMODEL 512
#define HNUM   8
#define KDIM   64
#define BSROWS (BDIM * SLEN)   // 8192
#define NBH    (BDIM * HNUM)   // 32

// ---------------- scratch (static device globals) ----------------
__device__ __align__(16) unsigned short g_xh[BSROWS * DMODEL], g_xl[BSROWS * DMODEL];
__device__ __align__(16) unsigned short g_wth[24 * KDIM * DMODEL], g_wtl[24 * KDIM * DMODEL]; // [hj][n][d]
__device__ __align__(16) unsigned short g_hkth[DMODEL * DMODEL], g_hktl[DMODEL * DMODEL];     // [n][e]
__device__ __align__(16) unsigned short g_qh[NBH * SLEN * KDIM], g_ql[NBH * SLEN * KDIM];     // [bh][s][d]
__device__ __align__(16) unsigned short g_kh[NBH * SLEN * KDIM], g_kl[NBH * SLEN * KDIM];     // [bh][t][d]
__device__ __align__(16) unsigned short g_vth[NBH * KDIM * SLEN], g_vtl[NBH * KDIM * SLEN];   // [bh][d][t]
__device__ __align__(16) unsigned short g_ch[BSROWS * DMODEL], g_cl[BSROWS * DMODEL];         // [row][e]

// ---------------- helpers ----------------
__device__ __forceinline__ unsigned smem_u32(const void* p) {
    unsigned a;
    asm("{ .reg .u64 t; cvta.to.shared.u64 t, %1; cvt.u32.u64 %0, t; }" : "=r"(a) : "l"(p));
    return a;
}
__device__ __forceinline__ void ldsm4(unsigned* r, unsigned a) {
    asm volatile("ldmatrix.sync.aligned.m8n8.x4.shared.b16 {%0,%1,%2,%3}, [%4];"
        : "=r"(r[0]), "=r"(r[1]), "=r"(r[2]), "=r"(r[3]) : "r"(a));
}
// A operand m16 x k16 at (m0, kbyte), row-major smem, stride bytes
__device__ __forceinline__ void ldA(unsigned* r, unsigned base, int stride, int m0, int kb, int lane) {
    int row = m0 + (lane & 7) + ((lane >> 3) & 1) * 8;
    int col = kb + (lane >> 4) * 16;
    ldsm4(r, base + row * stride + col);
}
// B operand: two n8 tiles (n0, n0+8) x k16 at kbyte; {r0,r1}=tile n0, {r2,r3}=tile n0+8
__device__ __forceinline__ void ldB(unsigned* r, unsigned base, int stride, int n0, int kb, int lane) {
    int row = n0 + (lane & 7) + (lane >> 4) * 8;
    int col = kb + ((lane >> 3) & 1) * 16;
    ldsm4(r, base + row * stride + col);
}
__device__ __forceinline__ void mma_bf16(float* c, const unsigned* a, unsigned b0, unsigned b1) {
    asm volatile("mma.sync.aligned.m16n8k16.row.col.f32.bf16.bf16.f32 "
        "{%0,%1,%2,%3}, {%4,%5,%6,%7}, {%8,%9}, {%0,%1,%2,%3};"
        : "+f"(c[0]), "+f"(c[1]), "+f"(c[2]), "+f"(c[3])
        : "r"(a[0]), "r"(a[1]), "r"(a[2]), "r"(a[3]), "r"(b0), "r"(b1));
}
__device__ __forceinline__ void splitbf(float x, unsigned short &h, unsigned short &l) {
    __nv_bfloat16 bh = __float2bfloat16(x);
    h = __bfloat16_as_ushort(bh);
    l = __bfloat16_as_ushort(__float2bfloat16(x - __bfloat162float(bh)));
}
__device__ __forceinline__ unsigned pk2(unsigned short a, unsigned short b) {
    return (unsigned)a | ((unsigned)b << 16);
}

// ================= convert kernels =================
__global__ void convert_x(const float* __restrict__ src, int n4) {
    int i = blockIdx.x * blockDim.x + threadIdx.x;
    if (i >= n4) return;
    float4 v = ((const float4*)src)[i];
    unsigned short h0,h1,h2,h3,l0,l1,l2,l3;
    splitbf(v.x,h0,l0); splitbf(v.y,h1,l1); splitbf(v.z,h2,l2); splitbf(v.w,h3,l3);
    ((uint2*)g_xh)[i] = make_uint2(pk2(h0,h1), pk2(h2,h3));
    ((uint2*)g_xl)[i] = make_uint2(pk2(l0,l1), pk2(l2,l3));
}
// src [mat][512][C] -> dst [mat][C][512]; which: 0 = w, 1 = hk
__global__ void transpose_split(const float* __restrict__ src, int which, int C, int nwork) {
    int i = blockIdx.x * blockDim.x + threadIdx.x;
    if (i >= nwork) return;
    int n = i % C, rest = i / C;
    int d8 = rest & 63, mat = rest >> 6;
    int d0 = d8 * 8;
    unsigned short h[8], l[8];
#pragma unroll
    for (int j = 0; j < 8; j++)
        splitbf(src[(size_t)mat * 512 * C + (size_t)(d0 + j) * C + n], h[j], l[j]);
    unsigned short* dh = which ? g_hkth : g_wth;
    unsigned short* dl = which ? g_hktl : g_wtl;
    size_t dst = (size_t)mat * C * 512 + (size_t)n * 512 + d0;
    *(uint4*)(dh + dst) = make_uint4(pk2(h[0],h[1]), pk2(h[2],h[3]), pk2(h[4],h[5]), pk2(h[6],h[7]));
    *(uint4*)(dl + dst) = make_uint4(pk2(l[0],l[1]), pk2(l[2],l[3]), pk2(l[4],l[5]), pk2(l[6],l[7]));
}

// ================= QKV projection =================
// grid (64, 24), block 256. C[128x64] = x[128x512] . wt[64x512]^T, split-bf16 3 passes.
#define QAH 0
#define QAL 18432
#define QBH 36864
#define QBL 46080
#define QKV_SMEM 55296
__global__ __launch_bounds__(256) void qkv_mma() {
    extern __shared__ char smc[];
    const unsigned sb = smem_u32(smc);
    const int tid = threadIdx.x, wid = tid >> 5, lane = tid & 31;
    const int wm = wid >> 1, wn = wid & 1;
    const int hj = blockIdx.y, row0 = blockIdx.x * 128;
    const int h = hj / 3, j = hj % 3;

    float acc[2][4][4];
#pragma unroll
    for (int a = 0; a < 2; a++)
#pragma unroll
        for (int b = 0; b < 4; b++)
#pragma unroll
            for (int c = 0; c < 4; c++) acc[a][b][c] = 0.f;

    for (int c8 = 0; c8 < 8; c8++) {
        if (c8) __syncthreads();
        const int d0 = c8 * 64;
#pragma unroll
        for (int t = 0; t < 4; t++) {               // A: 128 rows x 8 uint4
            int idx = tid + t * 256, r = idx >> 3, q = idx & 7;
            size_t so = (size_t)(row0 + r) * 512 + d0 + q * 8;
            *(uint4*)(smc + QAH + r * 144 + q * 16) = *(const uint4*)(g_xh + so);
            *(uint4*)(smc + QAL + r * 144 + q * 16) = *(const uint4*)(g_xl + so);
        }
#pragma unroll
        for (int t = 0; t < 2; t++) {               // B: 64 rows x 8 uint4
            int idx = tid + t * 256, r = idx >> 3, q = idx & 7;
            size_t so = (size_t)hj * 32768 + (size_t)r * 512 + d0 + q * 8;
            *(uint4*)(smc + QBH + r * 144 + q * 16) = *(const uint4*)(g_wth + so);
            *(uint4*)(smc + QBL + r * 144 + q * 16) = *(const uint4*)(g_wtl + so);
        }
        __syncthreads();
#pragma unroll
        for (int pass = 0; pass < 3; pass++) {
            unsigned ab = sb + ((pass < 2) ? QAH : QAL);
            unsigned bb = sb + ((pass == 1) ? QBL : QBH);
#pragma unroll
            for (int ks = 0; ks < 4; ks++) {
                const int kb = ks * 32;
                unsigned af0[4], af1[4];
                ldA(af0, ab, 144, wm * 32, kb, lane);
                ldA(af1, ab, 144, wm * 32 + 16, kb, lane);
#pragma unroll
                for (int g = 0; g < 2; g++) {
                    unsigned bf[4];
                    ldB(bf, bb, 144, wn * 32 + g * 16, kb, lane);
                    mma_bf16(acc[0][2*g],   af0, bf[0], bf[1]);
                    mma_bf16(acc[0][2*g+1], af0, bf[2], bf[3]);
                    mma_bf16(acc[1][2*g],   af1, bf[0], bf[1]);
                    mma_bf16(acc[1][2*g+1], af1, bf[2], bf[3]);
                }
            }
        }
    }

    if (j < 2) {   // Q or K: direct split write, [bh][s][d]
        const float sc = (j == 0) ? 0.125f : 1.0f;
        unsigned short* dh = (j == 0) ? g_qh : g_kh;
        unsigned short* dl = (j == 0) ? g_ql : g_kl;
#pragma unroll
        for (int mt = 0; mt < 2; mt++) {
            int r0 = row0 + wm * 32 + mt * 16 + (lane >> 2);
#pragma unroll
            for (int half = 0; half < 2; half++) {
                int r = r0 + half * 8;
                int b = r >> 11, s = r & (SLEN - 1);
                size_t base = ((size_t)(b * HNUM + h) * SLEN + s) * KDIM;
#pragma unroll
                for (int nt = 0; nt < 4; nt++) {
                    int col = wn * 32 + nt * 8 + (lane & 3) * 2;
                    float v0 = acc[mt][nt][half * 2 + 0] * sc;
                    float v1 = acc[mt][nt][half * 2 + 1] * sc;
                    unsigned short h0,l0,h1,l1;
                    splitbf(v0,h0,l0); splitbf(v1,h1,l1);
                    *(unsigned*)(dh + base + col) = pk2(h0, h1);
                    *(unsigned*)(dl + base + col) = pk2(l0, l1);
                }
            }
        }
    } else {       // V: stage transposed in smem then coalesced write [bh][d][t]
        __syncthreads();
#pragma unroll
        for (int mt = 0; mt < 2; mt++) {
#pragma unroll
            for (int half = 0; half < 2; half++) {
                int t = wm * 32 + mt * 16 + half * 8 + (lane >> 2);
#pragma unroll
                for (int nt = 0; nt < 4; nt++) {
                    int d = wn * 32 + nt * 8 + (lane & 3) * 2;
                    float v0 = acc[mt][nt][half * 2 + 0];
                    float v1 = acc[mt][nt][half * 2 + 1];
                    unsigned short h0,l0,h1,l1;
                    splitbf(v0,h0,l0); splitbf(v1,h1,l1);
                    *(unsigned short*)(smc + (d    ) * 272 + t * 2) = h0;
                    *(unsigned short*)(smc + (d + 1) * 272 + t * 2) = h1;
                    *(unsigned short*)(smc + 17408 + (d    ) * 272 + t * 2) = l0;
                    *(unsigned short*)(smc + 17408 + (d + 1) * 272 + t * 2) = l1;
                }
            }
        }
        __syncthreads();
        const int b = row0 >> 11, s0 = row0 & (SLEN - 1);
        const size_t vbase = ((size_t)(b * HNUM + h) * KDIM) * SLEN;
#pragma unroll
        for (int t = 0; t < 4; t++) {
            int idx = tid + t * 256, d = idx >> 4, q = idx & 15;
            size_t go = vbase + (size_t)d * SLEN + s0 + q * 8;
            *(uint4*)(g_vth + go) = *(const uint4*)(smc + d * 272 + q * 16);
            *(uint4*)(g_vtl + go) = *(const uint4*)(smc + 17408 + d * 272 + q * 16);
        }
    }
}

// ================= attention =================
// grid (16, 32), block 256. CTA: 128 q-rows, loop 16 tiles of 128 keys.
// P in split bf16: hi passes (Ph.Vh, Ph.Vl) then the P buffer is rewritten
// with Pl (kept packed in registers) for the Pl.Vh correction pass.
#define AQH 0
#define AQL 18432
#define AKH 36864
#define AKL 55296
#define AVH 73728
#define AVL 91136
#define APB 36864          /* P overlays K region (34816 <= 36864) */
#define ALS 108544
#define ATT_SMEM 109568
__global__ __launch_bounds__(256, 2) void attn_mma() {
    extern __shared__ char smc[];
    const unsigned sb = smem_u32(smc);
    float* ls = (float*)(smc + ALS);
    const int tid = threadIdx.x, wid = tid >> 5, lane = tid & 31;
    const int wm = wid >> 1, wn = wid & 1;
    const int bh = blockIdx.y, q0 = blockIdx.x * 128;
    const int b = bh >> 3, h = bh & 7;

    // load Q tile once (pre-scaled in qkv)
    {
        const size_t qb = ((size_t)bh * SLEN + q0) * KDIM;
#pragma unroll
        for (int t = 0; t < 4; t++) {
            int idx = tid + t * 256, r = idx >> 3, q = idx & 7;
            size_t so = qb + (size_t)r * KDIM + q * 8;
            *(uint4*)(smc + AQH + r * 144 + q * 16) = *(const uint4*)(g_qh + so);
            *(uint4*)(smc + AQL + r * 144 + q * 16) = *(const uint4*)(g_ql + so);
        }
    }

    float oacc[2][4][4];
    float lacc[2][2];
#pragma unroll
    for (int a = 0; a < 2; a++) {
        lacc[a][0] = lacc[a][1] = 0.f;
#pragma unroll
        for (int bq = 0; bq < 4; bq++)
#pragma unroll
            for (int c = 0; c < 4; c++) oacc[a][bq][c] = 0.f;
    }

    const size_t kbase = (size_t)bh * SLEN * KDIM;
    const size_t vbase = (size_t)bh * KDIM * SLEN;

    for (int it = 0; it < 16; it++) {
        if (it) __syncthreads();      // prev Pl.Vh reads done before overwriting K(P)/Vt
        const int t0 = it * 128;
#pragma unroll
        for (int t = 0; t < 4; t++) {                 // K tile
            int idx = tid + t * 256, r = idx >> 3, q = idx & 7;
            size_t so = kbase + (size_t)(t0 + r) * KDIM + q * 8;
            *(uint4*)(smc + AKH + r * 144 + q * 16) = *(const uint4*)(g_kh + so);
            *(uint4*)(smc + AKL + r * 144 + q * 16) = *(const uint4*)(g_kl + so);
        }
#pragma unroll
        for (int t = 0; t < 4; t++) {                 // Vt tile
            int idx = tid + t * 256, d = idx >> 4, q = idx & 15;
            size_t so = vbase + (size_t)d * SLEN + t0 + q * 8;
            *(uint4*)(smc + AVH + d * 272 + q * 16) = *(const uint4*)(g_vth + so);
            *(uint4*)(smc + AVL + d * 272 + q * 16) = *(const uint4*)(g_vtl + so);
        }
        __syncthreads();

        // ---- S = Q K^T, 3 split passes, warp tile 32q x 64t ----
        float sacc[2][8][4];
#pragma unroll
        for (int a = 0; a < 2; a++)
#pragma unroll
            for (int n = 0; n < 8; n++)
#pragma unroll
                for (int c = 0; c < 4; c++) sacc[a][n][c] = 0.f;
#pragma unroll
        for (int pass = 0; pass < 3; pass++) {
            unsigned ab = sb + ((pass < 2) ? AQH : AQL);
            unsigned bb = sb + ((pass == 1) ? AKL : AKH);
#pragma unroll
            for (int ks = 0; ks < 4; ks++) {
                const int kb = ks * 32;
                unsigned af0[4], af1[4];
                ldA(af0, ab, 144, wm * 32, kb, lane);
                ldA(af1, ab, 144, wm * 32 + 16, kb, lane);
#pragma unroll
                for (int g = 0; g < 4; g++) {
                    unsigned bf[4];
                    ldB(bf, bb, 144, wn * 64 + g * 16, kb, lane);
                    mma_bf16(sacc[0][2*g],   af0, bf[0], bf[1]);
                    mma_bf16(sacc[0][2*g+1], af0, bf[2], bf[3]);
                    mma_bf16(sacc[1][2*g],   af1, bf[0], bf[1]);
                    mma_bf16(sacc[1][2*g+1], af1, bf[2], bf[3]);
                }
            }
        }
        __syncthreads();   // all K reads done; P may overwrite K region

        // ---- p = exp(s) (fp32), rowsum from fp32 p, write Ph, stash Pl in regs ----
        unsigned plr[2][8][2];       // packed bf16x2 lo-parts
#pragma unroll
        for (int mt = 0; mt < 2; mt++) {
            int r0 = wm * 32 + mt * 16 + (lane >> 2);
#pragma unroll
            for (int nt = 0; nt < 8; nt++) {
                int col = wn * 64 + nt * 8 + (lane & 3) * 2;
                float p0 = __expf(sacc[mt][nt][0]);
                float p1 = __expf(sacc[mt][nt][1]);
                float p2 = __expf(sacc[mt][nt][2]);
                float p3 = __expf(sacc[mt][nt][3]);
                lacc[mt][0] += p0 + p1;
                lacc[mt][1] += p2 + p3;
                unsigned short h0,l0,h1,l1,h2,l2,h3,l3;
                splitbf(p0,h0,l0); splitbf(p1,h1,l1);
                splitbf(p2,h2,l2); splitbf(p3,h3,l3);
                *(unsigned*)(smc + APB + (r0    ) * 272 + col * 2) = pk2(h0, h1);
                *(unsigned*)(smc + APB + (r0 + 8) * 272 + col * 2) = pk2(h2, h3);
                plr[mt][nt][0] = pk2(l0, l1);
                plr[mt][nt][1] = pk2(l2, l3);
            }
        }
        __syncthreads();   // Ph visible

        // ---- O += Ph.Vh + Ph.Vl ----
#pragma unroll
        for (int ks = 0; ks < 8; ks++) {
            const int kb = ks * 32;
            unsigned af0[4], af1[4];
            ldA(af0, sb + APB, 272, wm * 32, kb, lane);
            ldA(af1, sb + APB, 272, wm * 32 + 16, kb, lane);
#pragma unroll
            for (int pass = 0; pass < 2; pass++) {
                unsigned bb = sb + (pass ? AVL : AVH);
#pragma unroll
                for (int g = 0; g < 2; g++) {
                    unsigned bf[4];
                    ldB(bf, bb, 272, wn * 32 + g * 16, kb, lane);
                    mma_bf16(oacc[0][2*g],   af0, bf[0], bf[1]);
                    mma_bf16(oacc[0][2*g+1], af0, bf[2], bf[3]);
                    mma_bf16(oacc[1][2*g],   af1, bf[0], bf[1]);
                    mma_bf16(oacc[1][2*g+1], af1, bf[2], bf[3]);
                }
            }
        }
        __syncthreads();   // Ph reads done; rewrite buffer with Pl

#pragma unroll
        for (int mt = 0; mt < 2; mt++) {
            int r0 = wm * 32 + mt * 16 + (lane >> 2);
#pragma unroll
            for (int nt = 0; nt < 8; nt++) {
                int col = wn * 64 + nt * 8 + (lane & 3) * 2;
                *(unsigned*)(smc + APB + (r0    ) * 272 + col * 2) = plr[mt][nt][0];
                *(unsigned*)(smc + APB + (r0 + 8) * 272 + col * 2) = plr[mt][nt][1];
            }
        }
        __syncthreads();   // Pl visible

        // ---- O += Pl.Vh ----
#pragma unroll
        for (int ks = 0; ks < 8; ks++) {
            const int kb = ks * 32;
            unsigned af0[4], af1[4];
            ldA(af0, sb + APB, 272, wm * 32, kb, lane);
            ldA(af1, sb + APB, 272, wm * 32 + 16, kb, lane);
#pragma unroll
            for (int g = 0; g < 2; g++) {
                unsigned bf[4];
                ldB(bf, sb + AVH, 272, wn * 32 + g * 16, kb, lane);
                mma_bf16(oacc[0][2*g],   af0, bf[0], bf[1]);
                mma_bf16(oacc[0][2*g+1], af0, bf[2], bf[3]);
                mma_bf16(oacc[1][2*g],   af1, bf[0], bf[1]);
                mma_bf16(oacc[1][2*g+1], af1, bf[2], bf[3]);
            }
        }
    }

    // ---- combine row sums across the two n-warps ----
#pragma unroll
    for (int mt = 0; mt < 2; mt++)
#pragma unroll
        for (int hf = 0; hf < 2; hf++) {
            float v = lacc[mt][hf];
            v += __shfl_xor_sync(0xffffffffu, v, 1);
            v += __shfl_xor_sync(0xffffffffu, v, 2);
            lacc[mt][hf] = v;
        }
    if ((lane & 3) == 0) {
#pragma unroll
        for (int mt = 0; mt < 2; mt++)
#pragma unroll
            for (int hf = 0; hf < 2; hf++)
                ls[wn * 128 + wm * 32 + mt * 16 + hf * 8 + (lane >> 2)] = lacc[mt][hf];
    }
    __syncthreads();

    // ---- normalize + split write to concat ----
#pragma unroll
    for (int mt = 0; mt < 2; mt++) {
        int r0 = wm * 32 + mt * 16 + (lane >> 2);
#pragma unroll
        for (int hf = 0; hf < 2; hf++) {
            int r = r0 + hf * 8;
            float inv = 1.f / (ls[r] + ls[128 + r]);
            size_t base = ((size_t)b * SLEN + q0 + r) * DMODEL + h * KDIM;
#pragma unroll
            for (int nt = 0; nt < 4; nt++) {
                int col = wn * 32 + nt * 8 + (lane & 3) * 2;
                float v0 = oacc[mt][nt][hf * 2 + 0] * inv;
                float v1 = oacc[mt][nt][hf * 2 + 1] * inv;
                unsigned short h0,l0,h1,l1;
                splitbf(v0,h0,l0); splitbf(v1,h1,l1);
                *(unsigned*)(g_ch + base + col) = pk2(h0, h1);
                *(unsigned*)(g_cl + base + col) = pk2(l0, l1);
            }
        }
    }
}

// ================= output projection =================
// grid (64, 4), block 256. out[128x128] = c[128x512] . hkt[128x512]^T
#define OAH 0
#define OAL 18432
#define OBH 36864
#define OBL 55296
#define OUT_SMEM 73728
__global__ __launch_bounds__(256) void outproj_mma(float* __restrict__ out) {
    extern __shared__ char smc[];
    const unsigned sb = smem_u32(smc);
    const int tid = threadIdx.x, wid = tid >> 5, lane = tid & 31;
    const int wm = wid >> 1, wn = wid & 1;
    const int row0 = blockIdx.x * 128, n0 = blockIdx.y * 128;

    float acc[2][8][4];
#pragma unroll
    for (int a = 0; a < 2; a++)
#pragma unroll
        for (int n = 0; n < 8; n++)
#pragma unroll
            for (int c = 0; c < 4; c++) acc[a][n][c] = 0.f;

    for (int c8 = 0; c8 < 8; c8++) {
        if (c8) __syncthreads();
        const int e0 = c8 * 64;
#pragma unroll
        for (int t = 0; t < 4; t++) {
            int idx = tid + t * 256, r = idx >> 3, q = idx & 7;
            size_t so = (size_t)(row0 + r) * 512 + e0 + q * 8;
            *(uint4*)(smc + OAH + r * 144 + q * 16) = *(const uint4*)(g_ch + so);
            *(uint4*)(smc + OAL + r * 144 + q * 16) = *(const uint4*)(g_cl + so);
        }
#pragma unroll
        for (int t = 0; t < 4; t++) {
            int idx = tid + t * 256, r = idx >> 3, q = idx & 7;
            size_t so = (size_t)(n0 + r) * 512 + e0 + q * 8;
            *(uint4*)(smc + OBH + r * 144 + q * 16) = *(const uint4*)(g_hkth + so);
            *(uint4*)(smc + OBL + r * 144 + q * 16) = *(const uint4*)(g_hktl + so);
        }
        __syncthreads();
#pragma unroll
        for (int pass = 0; pass < 3; pass++) {
            unsigned ab = sb + ((pass < 2) ? OAH : OAL);
            unsigned bb = sb + ((pass == 1) ? OBL : OBH);
#pragma unroll
            for (int ks = 0; ks < 4; ks++) {
                const int kb = ks * 32;
                unsigned af0[4], af1[4];
                ldA(af0, ab, 144, wm * 32, kb, lane);
                ldA(af1, ab, 144, wm * 32 + 16, kb, lane);
#pragma unroll
                for (int g = 0; g < 4; g++) {
                    unsigned bf[4];
                    ldB(bf, bb, 144, wn * 64 + g * 16, kb, lane);
                    mma_bf16(acc[0][2*g],   af0, bf[0], bf[1]);
                    mma_bf16(acc[0][2*g+1], af0, bf[2], bf[3]);
                    mma_bf16(acc[1][2*g],   af1, bf[0], bf[1]);
                    mma_bf16(acc[1][2*g+1], af1, bf[2], bf[3]);
                }
            }
        }
    }

#pragma unroll
    for (int mt = 0; mt < 2; mt++) {
        int r0 = row0 + wm * 32 + mt * 16 + (lane >> 2);
#pragma unroll
        for (int hf = 0; hf < 2; hf++) {
            size_t base = (size_t)(r0 + hf * 8) * DMODEL + n0;
#pragma unroll
            for (int nt = 0; nt < 8; nt++) {
                int col = wn * 64 + nt * 8 + (lane & 3) * 2;
                out[base + col]     = acc[mt][nt][hf * 2 + 0];
                out[base + col + 1] = acc[mt][nt][hf * 2 + 1];
            }
        }
    }
}

// =====================================================================
extern "C" void kernel_launch(void* const* d_in, const int* in_sizes, int n_in,
                              void* d_out, int out_size)
{
    const float* x    = (const float*)d_in[0];   // (4, 2048, 512)
    const float* kern = (const float*)d_in[1];   // (24, 512, 64)
    const float* hk   = (const float*)d_in[2];   // (512, 512)
    float* out = (float*)d_out;                  // (4, 2048, 512)

    cudaFuncSetAttribute(qkv_mma,     cudaFuncAttributeMaxDynamicSharedMemorySize, QKV_SMEM);
    cudaFuncSetAttribute(attn_mma,    cudaFuncAttributeMaxDynamicSharedMemorySize, ATT_SMEM);
    cudaFuncSetAttribute(outproj_mma, cudaFuncAttributeMaxDynamicSharedMemorySize, OUT_SMEM);

    const int n4x = BSROWS * DMODEL / 4;                     // 1048576
    convert_x<<<(n4x + 255) / 256, 256>>>(x, n4x);
    transpose_split<<<(24 * 64 * 64 + 255) / 256, 256>>>(kern, 0, 64, 24 * 64 * 64);
    transpose_split<<<(64 * 512 + 255) / 256, 256>>>(hk, 1, 512, 64 * 512);

    qkv_mma<<<dim3(BSROWS / 128, 24), 256, QKV_SMEM>>>();
    attn_mma<<<dim3(SLEN / 128, NBH), 256, ATT_SMEM>>>();
    outproj_mma<<<dim3(BSROWS / 128, DMODEL / 128), 256, OUT_SMEM>>>(out);
}

// round 5
// speedup vs baseline: 2.1502x; 1.0254x over previous
#include <cuda_runtime.h>
#include <cuda_bf16.h>

#define BDIM   4
#define SLEN   2048
#define DMODEL 512
#define HNUM   8
#define KDIM   64
#define BSROWS (BDIM * SLEN)   // 8192
#define NBH    (BDIM * HNUM)   // 32

// ---------------- scratch (static device globals) ----------------
__device__ __align__(16) unsigned short g_xh[BSROWS * DMODEL], g_xl[BSROWS * DMODEL];
__device__ __align__(16) unsigned short g_wth[24 * KDIM * DMODEL], g_wtl[24 * KDIM * DMODEL]; // [hj][n][d]
__device__ __align__(16) unsigned short g_hkth[DMODEL * DMODEL], g_hktl[DMODEL * DMODEL];     // [n][e]
__device__ __align__(16) unsigned short g_qh[NBH * SLEN * KDIM], g_ql[NBH * SLEN * KDIM];     // [bh][s][d]
__device__ __align__(16) unsigned short g_kh[NBH * SLEN * KDIM], g_kl[NBH * SLEN * KDIM];     // [bh][t][d]
__device__ __align__(16) unsigned short g_vth[NBH * KDIM * SLEN], g_vtl[NBH * KDIM * SLEN];   // [bh][d][t]
__device__ __align__(16) unsigned short g_ch[BSROWS * DMODEL], g_cl[BSROWS * DMODEL];         // [row][e]

// ---------------- helpers ----------------
__device__ __forceinline__ unsigned smem_u32(const void* p) {
    unsigned a;
    asm("{ .reg .u64 t; cvta.to.shared.u64 t, %1; cvt.u32.u64 %0, t; }" : "=r"(a) : "l"(p));
    return a;
}
__device__ __forceinline__ void ldsm4(unsigned* r, unsigned a) {
    asm volatile("ldmatrix.sync.aligned.m8n8.x4.shared.b16 {%0,%1,%2,%3}, [%4];"
        : "=r"(r[0]), "=r"(r[1]), "=r"(r[2]), "=r"(r[3]) : "r"(a));
}
// A operand m16 x k16 at (m0, kbyte), row-major smem, stride bytes
__device__ __forceinline__ void ldA(unsigned* r, unsigned base, int stride, int m0, int kb, int lane) {
    int row = m0 + (lane & 7) + ((lane >> 3) & 1) * 8;
    int col = kb + (lane >> 4) * 16;
    ldsm4(r, base + row * stride + col);
}
// B operand: two n8 tiles (n0, n0+8) x k16 at kbyte; {r0,r1}=tile n0, {r2,r3}=tile n0+8
__device__ __forceinline__ void ldB(unsigned* r, unsigned base, int stride, int n0, int kb, int lane) {
    int row = n0 + (lane & 7) + (lane >> 4) * 8;
    int col = kb + ((lane >> 3) & 1) * 16;
    ldsm4(r, base + row * stride + col);
}
__device__ __forceinline__ void mma_bf16(float* c, const unsigned* a, unsigned b0, unsigned b1) {
    asm volatile("mma.sync.aligned.m16n8k16.row.col.f32.bf16.bf16.f32 "
        "{%0,%1,%2,%3}, {%4,%5,%6,%7}, {%8,%9}, {%0,%1,%2,%3};"
        : "+f"(c[0]), "+f"(c[1]), "+f"(c[2]), "+f"(c[3])
        : "r"(a[0]), "r"(a[1]), "r"(a[2]), "r"(a[3]), "r"(b0), "r"(b1));
}
__device__ __forceinline__ void splitbf(float x, unsigned short &h, unsigned short &l) {
    __nv_bfloat16 bh = __float2bfloat16(x);
    h = __bfloat16_as_ushort(bh);
    l = __bfloat16_as_ushort(__float2bfloat16(x - __bfloat162float(bh)));
}
__device__ __forceinline__ unsigned pk2(unsigned short a, unsigned short b) {
    return (unsigned)a | ((unsigned)b << 16);
}

// ================= convert kernels =================
__global__ void convert_x(const float* __restrict__ src, int n4) {
    int i = blockIdx.x * blockDim.x + threadIdx.x;
    if (i >= n4) return;
    float4 v = ((const float4*)src)[i];
    unsigned short h0,h1,h2,h3,l0,l1,l2,l3;
    splitbf(v.x,h0,l0); splitbf(v.y,h1,l1); splitbf(v.z,h2,l2); splitbf(v.w,h3,l3);
    ((uint2*)g_xh)[i] = make_uint2(pk2(h0,h1), pk2(h2,h3));
    ((uint2*)g_xl)[i] = make_uint2(pk2(l0,l1), pk2(l2,l3));
}
// src [mat][512][C] -> dst [mat][C][512]; which: 0 = w, 1 = hk
__global__ void transpose_split(const float* __restrict__ src, int which, int C, int nwork) {
    int i = blockIdx.x * blockDim.x + threadIdx.x;
    if (i >= nwork) return;
    int n = i % C, rest = i / C;
    int d8 = rest & 63, mat = rest >> 6;
    int d0 = d8 * 8;
    unsigned short h[8], l[8];
#pragma unroll
    for (int j = 0; j < 8; j++)
        splitbf(src[(size_t)mat * 512 * C + (size_t)(d0 + j) * C + n], h[j], l[j]);
    unsigned short* dh = which ? g_hkth : g_wth;
    unsigned short* dl = which ? g_hktl : g_wtl;
    size_t dst = (size_t)mat * C * 512 + (size_t)n * 512 + d0;
    *(uint4*)(dh + dst) = make_uint4(pk2(h[0],h[1]), pk2(h[2],h[3]), pk2(h[4],h[5]), pk2(h[6],h[7]));
    *(uint4*)(dl + dst) = make_uint4(pk2(l[0],l[1]), pk2(l[2],l[3]), pk2(l[4],l[5]), pk2(l[6],l[7]));
}

// ================= QKV projection (fused per head) =================
// grid (64, 8), block 256. C[128x192] = x[128x512] . wt_head[192x512]^T.
// cols 0..63 = q (scaled 1/8), 64..127 = k, 128..191 = v (transposed out).
#define QA_H 0
#define QA_L 18432
#define QB_H 36864
#define QB_L 64512
#define QKV_SMEM 92160
__global__ __launch_bounds__(256, 2) void qkv_mma() {
    extern __shared__ char smc[];
    const unsigned sb = smem_u32(smc);
    const int tid = threadIdx.x, wid = tid >> 5, lane = tid & 31;
    const int wm = wid >> 1, wn = wid & 1;
    const int h = blockIdx.y, row0 = blockIdx.x * 128;

    float acc[2][12][4];
#pragma unroll
    for (int a = 0; a < 2; a++)
#pragma unroll
        for (int n = 0; n < 12; n++)
#pragma unroll
            for (int c = 0; c < 4; c++) acc[a][n][c] = 0.f;

    for (int c8 = 0; c8 < 8; c8++) {
        if (c8) __syncthreads();
        const int d0 = c8 * 64;
#pragma unroll
        for (int t = 0; t < 4; t++) {               // A: 128 rows x 8 uint4
            int idx = tid + t * 256, r = idx >> 3, q = idx & 7;
            size_t so = (size_t)(row0 + r) * 512 + d0 + q * 8;
            *(uint4*)(smc + QA_H + r * 144 + q * 16) = *(const uint4*)(g_xh + so);
            *(uint4*)(smc + QA_L + r * 144 + q * 16) = *(const uint4*)(g_xl + so);
        }
#pragma unroll
        for (int t = 0; t < 6; t++) {               // B: 192 rows x 8 uint4
            int idx = tid + t * 256, r = idx >> 3, q = idx & 7;
            size_t so = (size_t)(h * 192 + r) * 512 + d0 + q * 8;
            *(uint4*)(smc + QB_H + r * 144 + q * 16) = *(const uint4*)(g_wth + so);
            *(uint4*)(smc + QB_L + r * 144 + q * 16) = *(const uint4*)(g_wtl + so);
        }
        __syncthreads();
#pragma unroll
        for (int pass = 0; pass < 3; pass++) {
            unsigned ab = sb + ((pass < 2) ? QA_H : QA_L);
            unsigned bb = sb + ((pass == 1) ? QB_L : QB_H);
#pragma unroll
            for (int ks = 0; ks < 4; ks++) {
                const int kb = ks * 32;
                unsigned af0[4], af1[4];
                ldA(af0, ab, 144, wm * 32, kb, lane);
                ldA(af1, ab, 144, wm * 32 + 16, kb, lane);
#pragma unroll
                for (int g = 0; g < 6; g++) {
                    unsigned bf[4];
                    ldB(bf, bb, 144, wn * 96 + g * 16, kb, lane);
                    mma_bf16(acc[0][2*g],   af0, bf[0], bf[1]);
                    mma_bf16(acc[0][2*g+1], af0, bf[2], bf[3]);
                    mma_bf16(acc[1][2*g],   af1, bf[0], bf[1]);
                    mma_bf16(acc[1][2*g+1], af1, bf[2], bf[3]);
                }
            }
        }
    }
    __syncthreads();   // A region reuse for V staging

    // writeout
#pragma unroll
    for (int mt = 0; mt < 2; mt++) {
#pragma unroll
        for (int half = 0; half < 2; half++) {
            int tl = wm * 32 + mt * 16 + half * 8 + (lane >> 2);   // local row
            int r = row0 + tl;
            int b = r >> 11, s = r & (SLEN - 1);
#pragma unroll
            for (int nt = 0; nt < 12; nt++) {
                int col = wn * 96 + nt * 8 + (lane & 3) * 2;
                int j = col >> 6, cc = col & 63;
                float v0 = acc[mt][nt][half * 2 + 0];
                float v1 = acc[mt][nt][half * 2 + 1];
                if (j == 0) { v0 *= 0.125f; v1 *= 0.125f; }
                unsigned short h0,l0,h1,l1;
                splitbf(v0,h0,l0); splitbf(v1,h1,l1);
                if (j < 2) {
                    unsigned short* dh = (j == 0) ? g_qh : g_kh;
                    unsigned short* dl = (j == 0) ? g_ql : g_kl;
                    size_t base = ((size_t)(b * HNUM + h) * SLEN + s) * KDIM + cc;
                    *(unsigned*)(dh + base) = pk2(h0, h1);
                    *(unsigned*)(dl + base) = pk2(l0, l1);
                } else {   // V: stage [d][t] into dead A region
                    *(unsigned short*)(smc + (cc    ) * 272 + tl * 2) = h0;
                    *(unsigned short*)(smc + (cc + 1) * 272 + tl * 2) = h1;
                    *(unsigned short*)(smc + 17408 + (cc    ) * 272 + tl * 2) = l0;
                    *(unsigned short*)(smc + 17408 + (cc + 1) * 272 + tl * 2) = l1;
                }
            }
        }
    }
    __syncthreads();
    {
        const int b = row0 >> 11, s0 = row0 & (SLEN - 1);
        const size_t vbase = ((size_t)(b * HNUM + h) * KDIM) * SLEN;
#pragma unroll
        for (int t = 0; t < 4; t++) {
            int idx = tid + t * 256, d = idx >> 4, q = idx & 15;
            size_t go = vbase + (size_t)d * SLEN + s0 + q * 8;
            *(uint4*)(g_vth + go) = *(const uint4*)(smc + d * 272 + q * 16);
            *(uint4*)(g_vtl + go) = *(const uint4*)(smc + 17408 + d * 272 + q * 16);
        }
    }
}

// ================= attention (register-resident P) =================
// grid (16, 32), block 256. Warp w owns q-rows 16w..16w+15, full 128-t width.
// P (hi & lo) packed in registers as A-fragments -> no P smem, 2 syncs/iter.
#define AQH 0
#define AQL 18432
#define AKH 36864
#define AKL 55296
#define AVH 73728
#define AVL 91136
#define ATT_SMEM 108544
__global__ __launch_bounds__(256, 2) void attn_mma() {
    extern __shared__ char smc[];
    const unsigned sb = smem_u32(smc);
    const int tid = threadIdx.x, wid = tid >> 5, lane = tid & 31;
    const int m0 = wid * 16;
    const int bh = blockIdx.y, q0 = blockIdx.x * 128;
    const int b = bh >> 3, h = bh & 7;

    // load Q tile once (pre-scaled in qkv)
    {
        const size_t qb = ((size_t)bh * SLEN + q0) * KDIM;
#pragma unroll
        for (int t = 0; t < 4; t++) {
            int idx = tid + t * 256, r = idx >> 3, q = idx & 7;
            size_t so = qb + (size_t)r * KDIM + q * 8;
            *(uint4*)(smc + AQH + r * 144 + q * 16) = *(const uint4*)(g_qh + so);
            *(uint4*)(smc + AQL + r * 144 + q * 16) = *(const uint4*)(g_ql + so);
        }
    }

    float oacc[8][4];
    float ls0 = 0.f, ls1 = 0.f;
#pragma unroll
    for (int n = 0; n < 8; n++)
#pragma unroll
        for (int c = 0; c < 4; c++) oacc[n][c] = 0.f;

    const size_t kbase = (size_t)bh * SLEN * KDIM;
    const size_t vbase = (size_t)bh * KDIM * SLEN;

    for (int it = 0; it < 16; it++) {
        if (it) __syncthreads();      // prev iter's K/V reads done
        const int t0 = it * 128;
#pragma unroll
        for (int t = 0; t < 4; t++) {                 // K tile [t][d]
            int idx = tid + t * 256, r = idx >> 3, q = idx & 7;
            size_t so = kbase + (size_t)(t0 + r) * KDIM + q * 8;
            *(uint4*)(smc + AKH + r * 144 + q * 16) = *(const uint4*)(g_kh + so);
            *(uint4*)(smc + AKL + r * 144 + q * 16) = *(const uint4*)(g_kl + so);
        }
#pragma unroll
        for (int t = 0; t < 4; t++) {                 // Vt tile [d][t]
            int idx = tid + t * 256, d = idx >> 4, q = idx & 15;
            size_t so = vbase + (size_t)d * SLEN + t0 + q * 8;
            *(uint4*)(smc + AVH + d * 272 + q * 16) = *(const uint4*)(g_vth + so);
            *(uint4*)(smc + AVL + d * 272 + q * 16) = *(const uint4*)(g_vtl + so);
        }
        __syncthreads();

        // ---- S = Q K^T : warp rows m0..m0+15, cols 0..127, 3 split passes ----
        float sacc[16][4];
#pragma unroll
        for (int n = 0; n < 16; n++)
#pragma unroll
            for (int c = 0; c < 4; c++) sacc[n][c] = 0.f;
#pragma unroll
        for (int pass = 0; pass < 3; pass++) {
            unsigned ab = sb + ((pass < 2) ? AQH : AQL);
            unsigned bb = sb + ((pass == 1) ? AKL : AKH);
#pragma unroll
            for (int ks = 0; ks < 4; ks++) {
                const int kb = ks * 32;
                unsigned af[4];
                ldA(af, ab, 144, m0, kb, lane);
#pragma unroll
                for (int g = 0; g < 8; g++) {
                    unsigned bf[4];
                    ldB(bf, bb, 144, g * 16, kb, lane);
                    mma_bf16(sacc[2*g],   af, bf[0], bf[1]);
                    mma_bf16(sacc[2*g+1], af, bf[2], bf[3]);
                }
            }
        }

        // ---- p = exp(s); pack Ph/Pl directly as A-fragments; rowsums ----
        unsigned ph[8][4], pl[8][4];
#pragma unroll
        for (int nt = 0; nt < 16; nt++) {
            float p0 = __expf(sacc[nt][0]);
            float p1 = __expf(sacc[nt][1]);
            float p2 = __expf(sacc[nt][2]);
            float p3 = __expf(sacc[nt][3]);
            ls0 += p0 + p1;
            ls1 += p2 + p3;
            unsigned short h0,l0,h1,l1,h2,l2,h3,l3;
            splitbf(p0,h0,l0); splitbf(p1,h1,l1);
            splitbf(p2,h2,l2); splitbf(p3,h3,l3);
            int kc = nt >> 1, o = (nt & 1) * 2;
            ph[kc][o]     = pk2(h0, h1);
            ph[kc][o + 1] = pk2(h2, h3);
            pl[kc][o]     = pk2(l0, l1);
            pl[kc][o + 1] = pk2(l2, l3);
        }

        // ---- O += Ph.Vh + Pl.Vh + Ph.Vl (register A-frags, Vh reused) ----
#pragma unroll
        for (int ks = 0; ks < 8; ks++) {
            const int kb = ks * 32;
#pragma unroll
            for (int g = 0; g < 4; g++) {
                unsigned bfh[4], bfl[4];
                ldB(bfh, sb + AVH, 272, g * 16, kb, lane);
                mma_bf16(oacc[2*g],   ph[ks], bfh[0], bfh[1]);
                mma_bf16(oacc[2*g+1], ph[ks], bfh[2], bfh[3]);
                mma_bf16(oacc[2*g],   pl[ks], bfh[0], bfh[1]);
                mma_bf16(oacc[2*g+1], pl[ks], bfh[2], bfh[3]);
                ldB(bfl, sb + AVL, 272, g * 16, kb, lane);
                mma_bf16(oacc[2*g],   ph[ks], bfl[0], bfl[1]);
                mma_bf16(oacc[2*g+1], ph[ks], bfl[2], bfl[3]);
            }
        }
    }

    // ---- rowsum: quad-reduce (warp owns full rows) ----
    ls0 += __shfl_xor_sync(0xffffffffu, ls0, 1);
    ls0 += __shfl_xor_sync(0xffffffffu, ls0, 2);
    ls1 += __shfl_xor_sync(0xffffffffu, ls1, 1);
    ls1 += __shfl_xor_sync(0xffffffffu, ls1, 2);
    const float inv0 = 1.f / ls0, inv1 = 1.f / ls1;

    // ---- normalize + split write to concat ----
    const int r = m0 + (lane >> 2);
    const size_t base0 = ((size_t)b * SLEN + q0 + r) * DMODEL + h * KDIM;
    const size_t base1 = base0 + 8 * DMODEL;
#pragma unroll
    for (int nt = 0; nt < 8; nt++) {
        int col = nt * 8 + (lane & 3) * 2;
        float v0 = oacc[nt][0] * inv0, v1 = oacc[nt][1] * inv0;
        float v2 = oacc[nt][2] * inv1, v3 = oacc[nt][3] * inv1;
        unsigned short h0,l0,h1,l1,h2,l2,h3,l3;
        splitbf(v0,h0,l0); splitbf(v1,h1,l1);
        splitbf(v2,h2,l2); splitbf(v3,h3,l3);
        *(unsigned*)(g_ch + base0 + col) = pk2(h0, h1);
        *(unsigned*)(g_cl + base0 + col) = pk2(l0, l1);
        *(unsigned*)(g_ch + base1 + col) = pk2(h2, h3);
        *(unsigned*)(g_cl + base1 + col) = pk2(l2, l3);
    }
}

// ================= output projection =================
// grid (64, 4), block 256. out[128x128] = c[128x512] . hkt[128x512]^T
#define OAH 0
#define OAL 18432
#define OBH 36864
#define OBL 55296
#define OUT_SMEM 73728
__global__ __launch_bounds__(256, 2) void outproj_mma(float* __restrict__ out) {
    extern __shared__ char smc[];
    const unsigned sb = smem_u32(smc);
    const int tid = threadIdx.x, wid = tid >> 5, lane = tid & 31;
    const int wm = wid >> 1, wn = wid & 1;
    const int row0 = blockIdx.x * 128, n0 = blockIdx.y * 128;

    float acc[2][8][4];
#pragma unroll
    for (int a = 0; a < 2; a++)
#pragma unroll
        for (int n = 0; n < 8; n++)
#pragma unroll
            for (int c = 0; c < 4; c++) acc[a][n][c] = 0.f;

    for (int c8 = 0; c8 < 8; c8++) {
        if (c8) __syncthreads();
        const int e0 = c8 * 64;
#pragma unroll
        for (int t = 0; t < 4; t++) {
            int idx = tid + t * 256, r = idx >> 3, q = idx & 7;
            size_t so = (size_t)(row0 + r) * 512 + e0 + q * 8;
            *(uint4*)(smc + OAH + r * 144 + q * 16) = *(const uint4*)(g_ch + so);
            *(uint4*)(smc + OAL + r * 144 + q * 16) = *(const uint4*)(g_cl + so);
        }
#pragma unroll
        for (int t = 0; t < 4; t++) {
            int idx = tid + t * 256, r = idx >> 3, q = idx & 7;
            size_t so = (size_t)(n0 + r) * 512 + e0 + q * 8;
            *(uint4*)(smc + OBH + r * 144 + q * 16) = *(const uint4*)(g_hkth + so);
            *(uint4*)(smc + OBL + r * 144 + q * 16) = *(const uint4*)(g_hktl + so);
        }
        __syncthreads();
#pragma unroll
        for (int pass = 0; pass < 3; pass++) {
            unsigned ab = sb + ((pass < 2) ? OAH : OAL);
            unsigned bb = sb + ((pass == 1) ? OBL : OBH);
#pragma unroll
            for (int ks = 0; ks < 4; ks++) {
                const int kb = ks * 32;
                unsigned af0[4], af1[4];
                ldA(af0, ab, 144, wm * 32, kb, lane);
                ldA(af1, ab, 144, wm * 32 + 16, kb, lane);
#pragma unroll
                for (int g = 0; g < 4; g++) {
                    unsigned bf[4];
                    ldB(bf, bb, 144, wn * 64 + g * 16, kb, lane);
                    mma_bf16(acc[0][2*g],   af0, bf[0], bf[1]);
                    mma_bf16(acc[0][2*g+1], af0, bf[2], bf[3]);
                    mma_bf16(acc[1][2*g],   af1, bf[0], bf[1]);
                    mma_bf16(acc[1][2*g+1], af1, bf[2], bf[3]);
                }
            }
        }
    }

#pragma unroll
    for (int mt = 0; mt < 2; mt++) {
        int r0 = row0 + wm * 32 + mt * 16 + (lane >> 2);
#pragma unroll
        for (int hf = 0; hf < 2; hf++) {
            size_t base = (size_t)(r0 + hf * 8) * DMODEL + n0;
#pragma unroll
            for (int nt = 0; nt < 8; nt++) {
                int col = wn * 64 + nt * 8 + (lane & 3) * 2;
                out[base + col]     = acc[mt][nt][hf * 2 + 0];
                out[base + col + 1] = acc[mt][nt][hf * 2 + 1];
            }
        }
    }
}

// =====================================================================
extern "C" void kernel_launch(void* const* d_in, const int* in_sizes, int n_in,
                              void* d_out, int out_size)
{
    const float* x    = (const float*)d_in[0];   // (4, 2048, 512)
    const float* kern = (const float*)d_in[1];   // (24, 512, 64)
    const float* hk   = (const float*)d_in[2];   // (512, 512)
    float* out = (float*)d_out;                  // (4, 2048, 512)

    cudaFuncSetAttribute(qkv_mma,     cudaFuncAttributeMaxDynamicSharedMemorySize, QKV_SMEM);
    cudaFuncSetAttribute(attn_mma,    cudaFuncAttributeMaxDynamicSharedMemorySize, ATT_SMEM);
    cudaFuncSetAttribute(outproj_mma, cudaFuncAttributeMaxDynamicSharedMemorySize, OUT_SMEM);

    const int n4x = BSROWS * DMODEL / 4;                     // 1048576
    convert_x<<<(n4x + 255) / 256, 256>>>(x, n4x);
    transpose_split<<<(24 * 64 * 64 + 255) / 256, 256>>>(kern, 0, 64, 24 * 64 * 64);
    transpose_split<<<(64 * 512 + 255) / 256, 256>>>(hk, 1, 512, 64 * 512);

    qkv_mma<<<dim3(BSROWS / 128, HNUM), 256, QKV_SMEM>>>();
    attn_mma<<<dim3(SLEN / 128, NBH), 256, ATT_SMEM>>>();
    outproj_mma<<<dim3(BSROWS / 128, DMODEL / 128), 256, OUT_SMEM>>>(out);
}

// round 7
// speedup vs baseline: 2.8399x; 1.3207x over previous
#include <cuda_runtime.h>
#include <cuda_bf16.h>

#define BDIM   4
#define SLEN   2048
#define DMODEL 512
#define HNUM   8
#define KDIM   64
#define BSROWS (BDIM * SLEN)   // 8192
#define NBH    (BDIM * HNUM)   // 32

// ---------------- scratch (static device globals) ----------------
__device__ __align__(16) unsigned short g_xh[BSROWS * DMODEL], g_xl[BSROWS * DMODEL];
__device__ __align__(16) unsigned short g_wth[24 * KDIM * DMODEL], g_wtl[24 * KDIM * DMODEL]; // [hj][n][d]
__device__ __align__(16) unsigned short g_hkth[DMODEL * DMODEL], g_hktl[DMODEL * DMODEL];     // [n][e]
__device__ __align__(16) unsigned short g_qh[NBH * SLEN * KDIM], g_ql[NBH * SLEN * KDIM];     // [bh][s][d]
__device__ __align__(16) unsigned short g_kh[NBH * SLEN * KDIM], g_kl[NBH * SLEN * KDIM];     // [bh][t][d]
__device__ __align__(16) unsigned short g_vth[NBH * KDIM * SLEN], g_vtl[NBH * KDIM * SLEN];   // [bh][d][t]
__device__ __align__(16) unsigned short g_ch[BSROWS * DMODEL], g_cl[BSROWS * DMODEL];         // [row][e]

// ---------------- helpers ----------------
__device__ __forceinline__ unsigned smem_u32(const void* p) {
    unsigned a;
    asm("{ .reg .u64 t; cvta.to.shared.u64 t, %1; cvt.u32.u64 %0, t; }" : "=r"(a) : "l"(p));
    return a;
}
__device__ __forceinline__ void ldsm4(unsigned* r, unsigned a) {
    asm volatile("ldmatrix.sync.aligned.m8n8.x4.shared.b16 {%0,%1,%2,%3}, [%4];"
        : "=r"(r[0]), "=r"(r[1]), "=r"(r[2]), "=r"(r[3]) : "r"(a));
}
// A operand m16 x k16 at (m0, kbyte), row-major smem, stride bytes
__device__ __forceinline__ void ldA(unsigned* r, unsigned base, int stride, int m0, int kb, int lane) {
    int row = m0 + (lane & 7) + ((lane >> 3) & 1) * 8;
    int col = kb + (lane >> 4) * 16;
    ldsm4(r, base + row * stride + col);
}
// B operand: two n8 tiles (n0, n0+8) x k16 at kbyte; {r0,r1}=tile n0, {r2,r3}=tile n0+8
__device__ __forceinline__ void ldB(unsigned* r, unsigned base, int stride, int n0, int kb, int lane) {
    int row = n0 + (lane & 7) + (lane >> 4) * 8;
    int col = kb + ((lane >> 3) & 1) * 16;
    ldsm4(r, base + row * stride + col);
}
__device__ __forceinline__ void mma_bf16(float* c, const unsigned* a, unsigned b0, unsigned b1) {
    asm volatile("mma.sync.aligned.m16n8k16.row.col.f32.bf16.bf16.f32 "
        "{%0,%1,%2,%3}, {%4,%5,%6,%7}, {%8,%9}, {%0,%1,%2,%3};"
        : "+f"(c[0]), "+f"(c[1]), "+f"(c[2]), "+f"(c[3])
        : "r"(a[0]), "r"(a[1]), "r"(a[2]), "r"(a[3]), "r"(b0), "r"(b1));
}
__device__ __forceinline__ void splitbf(float x, unsigned short &h, unsigned short &l) {
    __nv_bfloat16 bh = __float2bfloat16(x);
    h = __bfloat16_as_ushort(bh);
    l = __bfloat16_as_ushort(__float2bfloat16(x - __bfloat162float(bh)));
}
__device__ __forceinline__ unsigned pk2(unsigned short a, unsigned short b) {
    return (unsigned)a | ((unsigned)b << 16);
}

// ================= convert kernels =================
__global__ void convert_x(const float* __restrict__ src, int n4) {
    int i = blockIdx.x * blockDim.x + threadIdx.x;
    if (i >= n4) return;
    float4 v = ((const float4*)src)[i];
    unsigned short h0,h1,h2,h3,l0,l1,l2,l3;
    splitbf(v.x,h0,l0); splitbf(v.y,h1,l1); splitbf(v.z,h2,l2); splitbf(v.w,h3,l3);
    ((uint2*)g_xh)[i] = make_uint2(pk2(h0,h1), pk2(h2,h3));
    ((uint2*)g_xl)[i] = make_uint2(pk2(l0,l1), pk2(l2,l3));
}
// src [mat][512][C] -> dst [mat][C][512]; which: 0 = w, 1 = hk
__global__ void transpose_split(const float* __restrict__ src, int which, int C, int nwork) {
    int i = blockIdx.x * blockDim.x + threadIdx.x;
    if (i >= nwork) return;
    int n = i % C, rest = i / C;
    int d8 = rest & 63, mat = rest >> 6;
    int d0 = d8 * 8;
    unsigned short h[8], l[8];
#pragma unroll
    for (int j = 0; j < 8; j++)
        splitbf(src[(size_t)mat * 512 * C + (size_t)(d0 + j) * C + n], h[j], l[j]);
    unsigned short* dh = which ? g_hkth : g_wth;
    unsigned short* dl = which ? g_hktl : g_wtl;
    size_t dst = (size_t)mat * C * 512 + (size_t)n * 512 + d0;
    *(uint4*)(dh + dst) = make_uint4(pk2(h[0],h[1]), pk2(h[2],h[3]), pk2(h[4],h[5]), pk2(h[6],h[7]));
    *(uint4*)(dl + dst) = make_uint4(pk2(l[0],l[1]), pk2(l[2],l[3]), pk2(l[4],l[5]), pk2(l[6],l[7]));
}

// ================= QKV projection (fused per head, 512 threads) =================
// grid (64, 8), block 512. C[128x192] = x[128x512] . wt_head[192x512]^T.
// Warp (wm,wn): rows wm*16..+15, cols wn*96..+95. acc = 48 floats/thread.
// cols 0..63 = q (scaled 1/8), 64..127 = k, 128..191 = v (transposed out).
#define QA_H 0
#define QA_L 18432
#define QB_H 36864
#define QB_L 64512
#define QKV_SMEM 92160
__global__ __launch_bounds__(512, 1) void qkv_mma() {
    extern __shared__ char smc[];
    const unsigned sb = smem_u32(smc);
    const int tid = threadIdx.x, wid = tid >> 5, lane = tid & 31;
    const int wm = wid >> 1, wn = wid & 1;
    const int h = blockIdx.y, row0 = blockIdx.x * 128;
    const int m0 = wm * 16, n0 = wn * 96;

    float acc[12][4];
#pragma unroll
    for (int n = 0; n < 12; n++)
#pragma unroll
        for (int c = 0; c < 4; c++) acc[n][c] = 0.f;

    for (int c8 = 0; c8 < 8; c8++) {
        if (c8) __syncthreads();
        const int d0 = c8 * 64;
#pragma unroll
        for (int t = 0; t < 2; t++) {               // A: 128 rows x 8 uint4 (hi+lo)
            int idx = tid + t * 512, r = idx >> 3, q = idx & 7;
            size_t so = (size_t)(row0 + r) * 512 + d0 + q * 8;
            *(uint4*)(smc + QA_H + r * 144 + q * 16) = *(const uint4*)(g_xh + so);
            *(uint4*)(smc + QA_L + r * 144 + q * 16) = *(const uint4*)(g_xl + so);
        }
#pragma unroll
        for (int t = 0; t < 3; t++) {               // B: 192 rows x 8 uint4
            int idx = tid + t * 512, r = idx >> 3, q = idx & 7;
            size_t so = (size_t)(h * 192 + r) * 512 + d0 + q * 8;
            *(uint4*)(smc + QB_H + r * 144 + q * 16) = *(const uint4*)(g_wth + so);
            *(uint4*)(smc + QB_L + r * 144 + q * 16) = *(const uint4*)(g_wtl + so);
        }
        __syncthreads();
#pragma unroll
        for (int ks = 0; ks < 4; ks++) {            // fused 3-pass: load frags once
            const int kb = ks * 32;
            unsigned ah[4], al[4];
            ldA(ah, sb + QA_H, 144, m0, kb, lane);
            ldA(al, sb + QA_L, 144, m0, kb, lane);
#pragma unroll
            for (int g = 0; g < 6; g++) {
                unsigned bh[4], bl[4];
                ldB(bh, sb + QB_H, 144, n0 + g * 16, kb, lane);
                ldB(bl, sb + QB_L, 144, n0 + g * 16, kb, lane);
                mma_bf16(acc[2*g],   ah, bh[0], bh[1]);
                mma_bf16(acc[2*g+1], ah, bh[2], bh[3]);
                mma_bf16(acc[2*g],   ah, bl[0], bl[1]);
                mma_bf16(acc[2*g+1], ah, bl[2], bl[3]);
                mma_bf16(acc[2*g],   al, bh[0], bh[1]);
                mma_bf16(acc[2*g+1], al, bh[2], bh[3]);
            }
        }
    }
    __syncthreads();   // A region reused for V staging

    // writeout
#pragma unroll
    for (int half = 0; half < 2; half++) {
        int tl = m0 + half * 8 + (lane >> 2);       // local row
        int r = row0 + tl;
        int b = r >> 11, s = r & (SLEN - 1);
#pragma unroll
        for (int nt = 0; nt < 12; nt++) {
            int col = n0 + nt * 8 + (lane & 3) * 2;
            int j = col >> 6, cc = col & 63;
            float v0 = acc[nt][half * 2 + 0];
            float v1 = acc[nt][half * 2 + 1];
            if (j == 0) { v0 *= 0.125f; v1 *= 0.125f; }
            unsigned short h0,l0,h1,l1;
            splitbf(v0,h0,l0); splitbf(v1,h1,l1);
            if (j < 2) {
                unsigned short* dh = (j == 0) ? g_qh : g_kh;
                unsigned short* dl = (j == 0) ? g_ql : g_kl;
                size_t base = ((size_t)(b * HNUM + h) * SLEN + s) * KDIM + cc;
                *(unsigned*)(dh + base) = pk2(h0, h1);
                *(unsigned*)(dl + base) = pk2(l0, l1);
            } else {   // V: stage [d][t] into dead A region
                *(unsigned short*)(smc + (cc    ) * 272 + tl * 2) = h0;
                *(unsigned short*)(smc + (cc + 1) * 272 + tl * 2) = h1;
                *(unsigned short*)(smc + 17408 + (cc    ) * 272 + tl * 2) = l0;
                *(unsigned short*)(smc + 17408 + (cc + 1) * 272 + tl * 2) = l1;
            }
        }
    }
    __syncthreads();
    {
        const int b = row0 >> 11, s0 = row0 & (SLEN - 1);
        const size_t vbase = ((size_t)(b * HNUM + h) * KDIM) * SLEN;
#pragma unroll
        for (int t = 0; t < 2; t++) {
            int idx = tid + t * 512, d = idx >> 4, q = idx & 15;
            size_t go = vbase + (size_t)d * SLEN + s0 + q * 8;
            *(uint4*)(g_vth + go) = *(const uint4*)(smc + d * 272 + q * 16);
            *(uint4*)(g_vtl + go) = *(const uint4*)(smc + 17408 + d * 272 + q * 16);
        }
    }
}

// ================= attention (register-resident P, fused S passes) =================
// grid (16, 32), block 256. Warp w owns q-rows 16w..16w+15, full 128-t width.
#define AQH 0
#define AQL 18432
#define AKH 36864
#define AKL 55296
#define AVH 73728
#define AVL 91136
#define ATT_SMEM 108544
__global__ __launch_bounds__(256, 2) void attn_mma() {
    extern __shared__ char smc[];
    const unsigned sb = smem_u32(smc);
    const int tid = threadIdx.x, wid = tid >> 5, lane = tid & 31;
    const int m0 = wid * 16;
    const int bh = blockIdx.y, q0 = blockIdx.x * 128;
    const int b = bh >> 3, h = bh & 7;

    // load Q tile once (pre-scaled in qkv)
    {
        const size_t qb = ((size_t)bh * SLEN + q0) * KDIM;
#pragma unroll
        for (int t = 0; t < 4; t++) {
            int idx = tid + t * 256, r = idx >> 3, q = idx & 7;
            size_t so = qb + (size_t)r * KDIM + q * 8;
            *(uint4*)(smc + AQH + r * 144 + q * 16) = *(const uint4*)(g_qh + so);
            *(uint4*)(smc + AQL + r * 144 + q * 16) = *(const uint4*)(g_ql + so);
        }
    }

    float oacc[8][4];
    float ls0 = 0.f, ls1 = 0.f;
#pragma unroll
    for (int n = 0; n < 8; n++)
#pragma unroll
        for (int c = 0; c < 4; c++) oacc[n][c] = 0.f;

    const size_t kbase = (size_t)bh * SLEN * KDIM;
    const size_t vbase = (size_t)bh * KDIM * SLEN;

    for (int it = 0; it < 16; it++) {
        if (it) __syncthreads();      // prev iter's K/V reads done
        const int t0 = it * 128;
#pragma unroll
        for (int t = 0; t < 4; t++) {                 // K tile [t][d]
            int idx = tid + t * 256, r = idx >> 3, q = idx & 7;
            size_t so = kbase + (size_t)(t0 + r) * KDIM + q * 8;
            *(uint4*)(smc + AKH + r * 144 + q * 16) = *(const uint4*)(g_kh + so);
            *(uint4*)(smc + AKL + r * 144 + q * 16) = *(const uint4*)(g_kl + so);
        }
#pragma unroll
        for (int t = 0; t < 4; t++) {                 // Vt tile [d][t]
            int idx = tid + t * 256, d = idx >> 4, q = idx & 15;
            size_t so = vbase + (size_t)d * SLEN + t0 + q * 8;
            *(uint4*)(smc + AVH + d * 272 + q * 16) = *(const uint4*)(g_vth + so);
            *(uint4*)(smc + AVL + d * 272 + q * 16) = *(const uint4*)(g_vtl + so);
        }
        __syncthreads();

        // ---- S = Q K^T : fused 3-pass, each fragment loaded once ----
        float sacc[16][4];
#pragma unroll
        for (int n = 0; n < 16; n++)
#pragma unroll
            for (int c = 0; c < 4; c++) sacc[n][c] = 0.f;
#pragma unroll
        for (int ks = 0; ks < 4; ks++) {
            const int kb = ks * 32;
            unsigned aqh[4], aql[4];
            ldA(aqh, sb + AQH, 144, m0, kb, lane);
            ldA(aql, sb + AQL, 144, m0, kb, lane);
#pragma unroll
            for (int g = 0; g < 8; g++) {
                unsigned bkh[4], bkl[4];
                ldB(bkh, sb + AKH, 144, g * 16, kb, lane);
                ldB(bkl, sb + AKL, 144, g * 16, kb, lane);
                mma_bf16(sacc[2*g],   aqh, bkh[0], bkh[1]);
                mma_bf16(sacc[2*g+1], aqh, bkh[2], bkh[3]);
                mma_bf16(sacc[2*g],   aqh, bkl[0], bkl[1]);
                mma_bf16(sacc[2*g+1], aqh, bkl[2], bkl[3]);
                mma_bf16(sacc[2*g],   aql, bkh[0], bkh[1]);
                mma_bf16(sacc[2*g+1], aql, bkh[2], bkh[3]);
            }
        }

        // ---- p = exp(s); pack Ph/Pl directly as A-fragments; rowsums ----
        unsigned ph[8][4], pl[8][4];
#pragma unroll
        for (int nt = 0; nt < 16; nt++) {
            float p0 = __expf(sacc[nt][0]);
            float p1 = __expf(sacc[nt][1]);
            float p2 = __expf(sacc[nt][2]);
            float p3 = __expf(sacc[nt][3]);
            ls0 += p0 + p1;
            ls1 += p2 + p3;
            unsigned short h0,l0,h1,l1,h2,l2,h3,l3;
            splitbf(p0,h0,l0); splitbf(p1,h1,l1);
            splitbf(p2,h2,l2); splitbf(p3,h3,l3);
            int kc = nt >> 1, o = (nt & 1) * 2;
            ph[kc][o]     = pk2(h0, h1);
            ph[kc][o + 1] = pk2(h2, h3);
            pl[kc][o]     = pk2(l0, l1);
            pl[kc][o + 1] = pk2(l2, l3);
        }

        // ---- O += Ph.Vh + Pl.Vh + Ph.Vl (register A-frags, Vh reused) ----
#pragma unroll
        for (int ks = 0; ks < 8; ks++) {
            const int kb = ks * 32;
#pragma unroll
            for (int g = 0; g < 4; g++) {
                unsigned bfh[4], bfl[4];
                ldB(bfh, sb + AVH, 272, g * 16, kb, lane);
                mma_bf16(oacc[2*g],   ph[ks], bfh[0], bfh[1]);
                mma_bf16(oacc[2*g+1], ph[ks], bfh[2], bfh[3]);
                mma_bf16(oacc[2*g],   pl[ks], bfh[0], bfh[1]);
                mma_bf16(oacc[2*g+1], pl[ks], bfh[2], bfh[3]);
                ldB(bfl, sb + AVL, 272, g * 16, kb, lane);
                mma_bf16(oacc[2*g],   ph[ks], bfl[0], bfl[1]);
                mma_bf16(oacc[2*g+1], ph[ks], bfl[2], bfl[3]);
            }
        }
    }

    // ---- rowsum: quad-reduce (warp owns full rows) ----
    ls0 += __shfl_xor_sync(0xffffffffu, ls0, 1);
    ls0 += __shfl_xor_sync(0xffffffffu, ls0, 2);
    ls1 += __shfl_xor_sync(0xffffffffu, ls1, 1);
    ls1 += __shfl_xor_sync(0xffffffffu, ls1, 2);
    const float inv0 = 1.f / ls0, inv1 = 1.f / ls1;

    // ---- normalize + split write to concat ----
    const int r = m0 + (lane >> 2);
    const size_t base0 = ((size_t)b * SLEN + q0 + r) * DMODEL + h * KDIM;
    const size_t base1 = base0 + 8 * DMODEL;
#pragma unroll
    for (int nt = 0; nt < 8; nt++) {
        int col = nt * 8 + (lane & 3) * 2;
        float v0 = oacc[nt][0] * inv0, v1 = oacc[nt][1] * inv0;
        float v2 = oacc[nt][2] * inv1, v3 = oacc[nt][3] * inv1;
        unsigned short h0,l0,h1,l1,h2,l2,h3,l3;
        splitbf(v0,h0,l0); splitbf(v1,h1,l1);
        splitbf(v2,h2,l2); splitbf(v3,h3,l3);
        *(unsigned*)(g_ch + base0 + col) = pk2(h0, h1);
        *(unsigned*)(g_cl + base0 + col) = pk2(l0, l1);
        *(unsigned*)(g_ch + base1 + col) = pk2(h2, h3);
        *(unsigned*)(g_cl + base1 + col) = pk2(l2, l3);
    }
}

// ================= output projection =================
// grid (64, 4), block 256. out[128x128] = c[128x512] . hkt[128x512]^T
#define OAH 0
#define OAL 18432
#define OBH 36864
#define OBL 55296
#define OUT_SMEM 73728
__global__ __launch_bounds__(256, 2) void outproj_mma(float* __restrict__ out) {
    extern __shared__ char smc[];
    const unsigned sb = smem_u32(smc);
    const int tid = threadIdx.x, wid = tid >> 5, lane = tid & 31;
    const int wm = wid >> 1, wn = wid & 1;
    const int row0 = blockIdx.x * 128, n0 = blockIdx.y * 128;

    float acc[2][8][4];
#pragma unroll
    for (int a = 0; a < 2; a++)
#pragma unroll
        for (int n = 0; n < 8; n++)
#pragma unroll
            for (int c = 0; c < 4; c++) acc[a][n][c] = 0.f;

    for (int c8 = 0; c8 < 8; c8++) {
        if (c8) __syncthreads();
        const int e0 = c8 * 64;
#pragma unroll
        for (int t = 0; t < 4; t++) {
            int idx = tid + t * 256, r = idx >> 3, q = idx & 7;
            size_t so = (size_t)(row0 + r) * 512 + e0 + q * 8;
            *(uint4*)(smc + OAH + r * 144 + q * 16) = *(const uint4*)(g_ch + so);
            *(uint4*)(smc + OAL + r * 144 + q * 16) = *(const uint4*)(g_cl + so);
        }
#pragma unroll
        for (int t = 0; t < 4; t++) {
            int idx = tid + t * 256, r = idx >> 3, q = idx & 7;
            size_t so = (size_t)(n0 + r) * 512 + e0 + q * 8;
            *(uint4*)(smc + OBH + r * 144 + q * 16) = *(const uint4*)(g_hkth + so);
            *(uint4*)(smc + OBL + r * 144 + q * 16) = *(const uint4*)(g_hktl + so);
        }
        __syncthreads();
#pragma unroll
        for (int ks = 0; ks < 4; ks++) {            // fused 3-pass
            const int kb = ks * 32;
            unsigned ah0[4], ah1[4], al0[4], al1[4];
            ldA(ah0, sb + OAH, 144, wm * 32,      kb, lane);
            ldA(ah1, sb + OAH, 144, wm * 32 + 16, kb, lane);
            ldA(al0, sb + OAL, 144, wm * 32,      kb, lane);
            ldA(al1, sb + OAL, 144, wm * 32 + 16, kb, lane);
#pragma unroll
            for (int g = 0; g < 4; g++) {
                unsigned bh[4], bl[4];
                ldB(bh, sb + OBH, 144, wn * 64 + g * 16, kb, lane);
                ldB(bl, sb + OBL, 144, wn * 64 + g * 16, kb, lane);
                mma_bf16(acc[0][2*g],   ah0, bh[0], bh[1]);
                mma_bf16(acc[0][2*g+1], ah0, bh[2], bh[3]);
                mma_bf16(acc[1][2*g],   ah1, bh[0], bh[1]);
                mma_bf16(acc[1][2*g+1], ah1, bh[2], bh[3]);
                mma_bf16(acc[0][2*g],   ah0, bl[0], bl[1]);
                mma_bf16(acc[0][2*g+1], ah0, bl[2], bl[3]);
                mma_bf16(acc[1][2*g],   ah1, bl[0], bl[1]);
                mma_bf16(acc[1][2*g+1], ah1, bl[2], bl[3]);
                mma_bf16(acc[0][2*g],   al0, bh[0], bh[1]);
                mma_bf16(acc[0][2*g+1], al0, bh[2], bh[3]);
                mma_bf16(acc[1][2*g],   al1, bh[0], bh[1]);
                mma_bf16(acc[1][2*g+1], al1, bh[2], bh[3]);
            }
        }
    }

#pragma unroll
    for (int mt = 0; mt < 2; mt++) {
        int r0 = row0 + wm * 32 + mt * 16 + (lane >> 2);
#pragma unroll
        for (int hf = 0; hf < 2; hf++) {
            size_t base = (size_t)(r0 + hf * 8) * DMODEL + n0;
#pragma unroll
            for (int nt = 0; nt < 8; nt++) {
                int col = wn * 64 + nt * 8 + (lane & 3) * 2;
                out[base + col]     = acc[mt][nt][hf * 2 + 0];
                out[base + col + 1] = acc[mt][nt][hf * 2 + 1];
            }
        }
    }
}

// =====================================================================
extern "C" void kernel_launch(void* const* d_in, const int* in_sizes, int n_in,
                              void* d_out, int out_size)
{
    const float* x    = (const float*)d_in[0];   // (4, 2048, 512)
    const float* kern = (const float*)d_in[1];   // (24, 512, 64)
    const float* hk   = (const float*)d_in[2];   // (512, 512)
    float* out = (float*)d_out;                  // (4, 2048, 512)

    cudaFuncSetAttribute(qkv_mma,     cudaFuncAttributeMaxDynamicSharedMemorySize, QKV_SMEM);
    cudaFuncSetAttribute(attn_mma,    cudaFuncAttributeMaxDynamicSharedMemorySize, ATT_SMEM);
    cudaFuncSetAttribute(outproj_mma, cudaFuncAttributeMaxDynamicSharedMemorySize, OUT_SMEM);

    const int n4x = BSROWS * DMODEL / 4;                     // 1048576
    convert_x<<<(n4x + 255) / 256, 256>>>(x, n4x);
    transpose_split<<<(24 * 64 * 64 + 255) / 256, 256>>>(kern, 0, 64, 24 * 64 * 64);
    transpose_split<<<(64 * 512 + 255) / 256, 256>>>(hk, 1, 512, 64 * 512);

    qkv_mma<<<dim3(BSROWS / 128, HNUM), 512, QKV_SMEM>>>();
    attn_mma<<<dim3(SLEN / 128, NBH), 256, ATT_SMEM>>>();
    outproj_mma<<<dim3(BSROWS / 128, DMODEL / 128), 256, OUT_SMEM>>>(out);
}

// round 8
// speedup vs baseline: 2.9406x; 1.0355x over previous
#include <cuda_runtime.h>
#include <cuda_bf16.h>

#define BDIM   4
#define SLEN   2048
#define DMODEL 512
#define HNUM   8
#define KDIM   64
#define BSROWS (BDIM * SLEN)   // 8192
#define NBH    (BDIM * HNUM)   // 32

// ---------------- scratch (static device globals) ----------------
__device__ __align__(16) unsigned short g_xh[BSROWS * DMODEL], g_xl[BSROWS * DMODEL];
__device__ __align__(16) unsigned short g_wth[24 * KDIM * DMODEL], g_wtl[24 * KDIM * DMODEL]; // [hj][n][d]
__device__ __align__(16) unsigned short g_hkth[DMODEL * DMODEL], g_hktl[DMODEL * DMODEL];     // [n][e]
__device__ __align__(16) unsigned short g_qh[NBH * SLEN * KDIM], g_ql[NBH * SLEN * KDIM];     // [bh][s][d]
__device__ __align__(16) unsigned short g_kh[NBH * SLEN * KDIM], g_kl[NBH * SLEN * KDIM];     // [bh][t][d]
__device__ __align__(16) unsigned short g_vth[NBH * KDIM * SLEN], g_vtl[NBH * KDIM * SLEN];   // [bh][d][t]
__device__ __align__(16) unsigned short g_ch[BSROWS * DMODEL], g_cl[BSROWS * DMODEL];         // [row][e]

// ---------------- helpers ----------------
__device__ __forceinline__ unsigned smem_u32(const void* p) {
    unsigned a;
    asm("{ .reg .u64 t; cvta.to.shared.u64 t, %1; cvt.u32.u64 %0, t; }" : "=r"(a) : "l"(p));
    return a;
}
#define CP16(dst, src) \
    asm volatile("cp.async.cg.shared.global [%0], [%1], 16;" :: "r"(dst), "l"(src))
#define CPCOMMIT() asm volatile("cp.async.commit_group;" ::: "memory")
#define CPWAIT0()  asm volatile("cp.async.wait_group 0;" ::: "memory")
#define CPWAIT1()  asm volatile("cp.async.wait_group 1;" ::: "memory")

__device__ __forceinline__ void ldsm4(unsigned* r, unsigned a) {
    asm volatile("ldmatrix.sync.aligned.m8n8.x4.shared.b16 {%0,%1,%2,%3}, [%4];"
        : "=r"(r[0]), "=r"(r[1]), "=r"(r[2]), "=r"(r[3]) : "r"(a));
}
// A operand m16 x k16 at (m0, kbyte), row-major smem, stride bytes
__device__ __forceinline__ void ldA(unsigned* r, unsigned base, int stride, int m0, int kb, int lane) {
    int row = m0 + (lane & 7) + ((lane >> 3) & 1) * 8;
    int col = kb + (lane >> 4) * 16;
    ldsm4(r, base + row * stride + col);
}
// B operand: two n8 tiles (n0, n0+8) x k16 at kbyte
__device__ __forceinline__ void ldB(unsigned* r, unsigned base, int stride, int n0, int kb, int lane) {
    int row = n0 + (lane & 7) + (lane >> 4) * 8;
    int col = kb + ((lane >> 3) & 1) * 16;
    ldsm4(r, base + row * stride + col);
}
__device__ __forceinline__ void mma_bf16(float* c, const unsigned* a, unsigned b0, unsigned b1) {
    asm volatile("mma.sync.aligned.m16n8k16.row.col.f32.bf16.bf16.f32 "
        "{%0,%1,%2,%3}, {%4,%5,%6,%7}, {%8,%9}, {%0,%1,%2,%3};"
        : "+f"(c[0]), "+f"(c[1]), "+f"(c[2]), "+f"(c[3])
        : "r"(a[0]), "r"(a[1]), "r"(a[2]), "r"(a[3]), "r"(b0), "r"(b1));
}
__device__ __forceinline__ void splitbf(float x, unsigned short &h, unsigned short &l) {
    __nv_bfloat16 bh = __float2bfloat16(x);
    h = __bfloat16_as_ushort(bh);
    l = __bfloat16_as_ushort(__float2bfloat16(x - __bfloat162float(bh)));
}
__device__ __forceinline__ unsigned pk2(unsigned short a, unsigned short b) {
    return (unsigned)a | ((unsigned)b << 16);
}

// ================= convert kernels =================
__global__ void convert_x(const float* __restrict__ src, int n4) {
    int i = blockIdx.x * blockDim.x + threadIdx.x;
    if (i >= n4) return;
    float4 v = ((const float4*)src)[i];
    unsigned short h0,h1,h2,h3,l0,l1,l2,l3;
    splitbf(v.x,h0,l0); splitbf(v.y,h1,l1); splitbf(v.z,h2,l2); splitbf(v.w,h3,l3);
    ((uint2*)g_xh)[i] = make_uint2(pk2(h0,h1), pk2(h2,h3));
    ((uint2*)g_xl)[i] = make_uint2(pk2(l0,l1), pk2(l2,l3));
}
// src [mat][512][C] -> dst [mat][C][512]; which: 0 = w, 1 = hk
__global__ void transpose_split(const float* __restrict__ src, int which, int C, int nwork) {
    int i = blockIdx.x * blockDim.x + threadIdx.x;
    if (i >= nwork) return;
    int n = i % C, rest = i / C;
    int d8 = rest & 63, mat = rest >> 6;
    int d0 = d8 * 8;
    unsigned short h[8], l[8];
#pragma unroll
    for (int j = 0; j < 8; j++)
        splitbf(src[(size_t)mat * 512 * C + (size_t)(d0 + j) * C + n], h[j], l[j]);
    unsigned short* dh = which ? g_hkth : g_wth;
    unsigned short* dl = which ? g_hktl : g_wtl;
    size_t dst = (size_t)mat * C * 512 + (size_t)n * 512 + d0;
    *(uint4*)(dh + dst) = make_uint4(pk2(h[0],h[1]), pk2(h[2],h[3]), pk2(h[4],h[5]), pk2(h[6],h[7]));
    *(uint4*)(dl + dst) = make_uint4(pk2(l[0],l[1]), pk2(l[2],l[3]), pk2(l[4],l[5]), pk2(l[6],l[7]));
}

// ================= QKV projection (fused, 512 thr, cp.async 2-stage) =================
// grid (64, 8). C[128x192] = x[128x512] . wt_head[192x512]^T.
// stage layout (92160 B each): A_H 0, A_L 18432, B_H 36864, B_L 64512
#define QSTG 92160
#define QKV_SMEM (2 * QSTG)     // 184320
__global__ __launch_bounds__(512, 1) void qkv_mma() {
    extern __shared__ char smc[];
    const unsigned sb = smem_u32(smc);
    const int tid = threadIdx.x, wid = tid >> 5, lane = tid & 31;
    const int wm = wid >> 1, wn = wid & 1;
    const int h = blockIdx.y, row0 = blockIdx.x * 128;
    const int m0 = wm * 16, n0 = wn * 96;

    auto issue = [&](int c8) {
        const unsigned ab = sb + (c8 & 1) * QSTG;
        const int d0 = c8 * 64;
#pragma unroll
        for (int t = 0; t < 2; t++) {               // A: 128 rows x 8 x 16B (hi+lo)
            int idx = tid + t * 512, r = idx >> 3, q = idx & 7;
            size_t so = (size_t)(row0 + r) * 512 + d0 + q * 8;
            CP16(ab + r * 144 + q * 16, g_xh + so);
            CP16(ab + 18432 + r * 144 + q * 16, g_xl + so);
        }
#pragma unroll
        for (int t = 0; t < 3; t++) {               // B: 192 rows
            int idx = tid + t * 512, r = idx >> 3, q = idx & 7;
            size_t so = (size_t)(h * 192 + r) * 512 + d0 + q * 8;
            CP16(ab + 36864 + r * 144 + q * 16, g_wth + so);
            CP16(ab + 64512 + r * 144 + q * 16, g_wtl + so);
        }
    };

    float acc[12][4];
#pragma unroll
    for (int n = 0; n < 12; n++)
#pragma unroll
        for (int c = 0; c < 4; c++) acc[n][c] = 0.f;

    issue(0); CPCOMMIT();
    for (int c8 = 0; c8 < 8; c8++) {
        if (c8 < 7) { issue(c8 + 1); CPCOMMIT(); CPWAIT1(); } else { CPWAIT0(); }
        __syncthreads();
        const unsigned ab = sb + (c8 & 1) * QSTG;
#pragma unroll
        for (int ks = 0; ks < 4; ks++) {
            const int kb = ks * 32;
            unsigned ah[4], al[4];
            ldA(ah, ab, 144, m0, kb, lane);
            ldA(al, ab + 18432, 144, m0, kb, lane);
#pragma unroll
            for (int g = 0; g < 6; g++) {
                unsigned bh[4], bl[4];
                ldB(bh, ab + 36864, 144, n0 + g * 16, kb, lane);
                ldB(bl, ab + 64512, 144, n0 + g * 16, kb, lane);
                mma_bf16(acc[2*g],   ah, bh[0], bh[1]);
                mma_bf16(acc[2*g+1], ah, bh[2], bh[3]);
                mma_bf16(acc[2*g],   ah, bl[0], bl[1]);
                mma_bf16(acc[2*g+1], ah, bl[2], bl[3]);
                mma_bf16(acc[2*g],   al, bh[0], bh[1]);
                mma_bf16(acc[2*g+1], al, bh[2], bh[3]);
            }
        }
        __syncthreads();     // all reads done before this buffer is refilled
    }

    // writeout (stage-0 A region is free: last compute used stage 1)
#pragma unroll
    for (int half = 0; half < 2; half++) {
        int tl = m0 + half * 8 + (lane >> 2);       // local row
        int r = row0 + tl;
        int b = r >> 11, s = r & (SLEN - 1);
#pragma unroll
        for (int nt = 0; nt < 12; nt++) {
            int col = n0 + nt * 8 + (lane & 3) * 2;
            int j = col >> 6, cc = col & 63;
            float v0 = acc[nt][half * 2 + 0];
            float v1 = acc[nt][half * 2 + 1];
            if (j == 0) { v0 *= 0.125f; v1 *= 0.125f; }
            unsigned short h0,l0,h1,l1;
            splitbf(v0,h0,l0); splitbf(v1,h1,l1);
            if (j < 2) {
                unsigned short* dh = (j == 0) ? g_qh : g_kh;
                unsigned short* dl = (j == 0) ? g_ql : g_kl;
                size_t base = ((size_t)(b * HNUM + h) * SLEN + s) * KDIM + cc;
                *(unsigned*)(dh + base) = pk2(h0, h1);
                *(unsigned*)(dl + base) = pk2(l0, l1);
            } else {   // V: stage [d][t] into free stage-0 region
                *(unsigned short*)(smc + (cc    ) * 272 + tl * 2) = h0;
                *(unsigned short*)(smc + (cc + 1) * 272 + tl * 2) = h1;
                *(unsigned short*)(smc + 17408 + (cc    ) * 272 + tl * 2) = l0;
                *(unsigned short*)(smc + 17408 + (cc + 1) * 272 + tl * 2) = l1;
            }
        }
    }
    __syncthreads();
    {
        const int b = row0 >> 11, s0 = row0 & (SLEN - 1);
        const size_t vbase = ((size_t)(b * HNUM + h) * KDIM) * SLEN;
#pragma unroll
        for (int t = 0; t < 2; t++) {
            int idx = tid + t * 512, d = idx >> 4, q = idx & 15;
            size_t go = vbase + (size_t)d * SLEN + s0 + q * 8;
            *(uint4*)(g_vth + go) = *(const uint4*)(smc + d * 272 + q * 16);
            *(uint4*)(g_vtl + go) = *(const uint4*)(smc + 17408 + d * 272 + q * 16);
        }
    }
}

// ================= attention (register P, cp.async 2-stage K/V) =================
// grid (16, 32), block 256, 1 CTA/SM. Warp w owns q-rows 16w..16w+15.
// smem: Q_H 0, Q_L 18432; stage s at 36864 + s*71680:
//   K_H +0, K_L +18432, V_H +36864, V_L +54272
#define ASTG0 36864
#define ASTG  71680
#define ATT_SMEM (ASTG0 + 2 * ASTG)   // 180224
__global__ __launch_bounds__(256, 1) void attn_mma() {
    extern __shared__ char smc[];
    const unsigned sb = smem_u32(smc);
    const int tid = threadIdx.x, wid = tid >> 5, lane = tid & 31;
    const int m0 = wid * 16;
    const int bh = blockIdx.y, q0 = blockIdx.x * 128;
    const int b = bh >> 3, h = bh & 7;

    const size_t kbase = (size_t)bh * SLEN * KDIM;
    const size_t vbase = (size_t)bh * KDIM * SLEN;

    auto issue_kv = [&](int it) {
        const unsigned stb = sb + ASTG0 + (it & 1) * ASTG;
        const int t0 = it * 128;
#pragma unroll
        for (int t = 0; t < 4; t++) {                 // K tile [t][d]
            int idx = tid + t * 256, r = idx >> 3, q = idx & 7;
            size_t so = kbase + (size_t)(t0 + r) * KDIM + q * 8;
            CP16(stb + r * 144 + q * 16, g_kh + so);
            CP16(stb + 18432 + r * 144 + q * 16, g_kl + so);
        }
#pragma unroll
        for (int t = 0; t < 4; t++) {                 // Vt tile [d][t]
            int idx = tid + t * 256, d = idx >> 4, q = idx & 15;
            size_t so = vbase + (size_t)d * SLEN + t0 + q * 8;
            CP16(stb + 36864 + d * 272 + q * 16, g_vth + so);
            CP16(stb + 54272 + d * 272 + q * 16, g_vtl + so);
        }
    };

    // prologue: Q + stage 0 in one group
    {
        const size_t qb = ((size_t)bh * SLEN + q0) * KDIM;
#pragma unroll
        for (int t = 0; t < 4; t++) {
            int idx = tid + t * 256, r = idx >> 3, q = idx & 7;
            size_t so = qb + (size_t)r * KDIM + q * 8;
            CP16(sb + r * 144 + q * 16, g_qh + so);
            CP16(sb + 18432 + r * 144 + q * 16, g_ql + so);
        }
        issue_kv(0); CPCOMMIT();
    }

    float oacc[8][4];
    float ls0 = 0.f, ls1 = 0.f;
#pragma unroll
    for (int n = 0; n < 8; n++)
#pragma unroll
        for (int c = 0; c < 4; c++) oacc[n][c] = 0.f;

    for (int it = 0; it < 16; it++) {
        if (it < 15) { issue_kv(it + 1); CPCOMMIT(); CPWAIT1(); } else { CPWAIT0(); }
        __syncthreads();
        const unsigned stb = sb + ASTG0 + (it & 1) * ASTG;

        // ---- S = Q K^T : fused 3-pass ----
        float sacc[16][4];
#pragma unroll
        for (int n = 0; n < 16; n++)
#pragma unroll
            for (int c = 0; c < 4; c++) sacc[n][c] = 0.f;
#pragma unroll
        for (int ks = 0; ks < 4; ks++) {
            const int kb = ks * 32;
            unsigned aqh[4], aql[4];
            ldA(aqh, sb, 144, m0, kb, lane);
            ldA(aql, sb + 18432, 144, m0, kb, lane);
#pragma unroll
            for (int g = 0; g < 8; g++) {
                unsigned bkh[4], bkl[4];
                ldB(bkh, stb, 144, g * 16, kb, lane);
                ldB(bkl, stb + 18432, 144, g * 16, kb, lane);
                mma_bf16(sacc[2*g],   aqh, bkh[0], bkh[1]);
                mma_bf16(sacc[2*g+1], aqh, bkh[2], bkh[3]);
                mma_bf16(sacc[2*g],   aqh, bkl[0], bkl[1]);
                mma_bf16(sacc[2*g+1], aqh, bkl[2], bkl[3]);
                mma_bf16(sacc[2*g],   aql, bkh[0], bkh[1]);
                mma_bf16(sacc[2*g+1], aql, bkh[2], bkh[3]);
            }
        }

        // ---- p = exp(s); pack Ph/Pl as A-fragments; rowsums ----
        unsigned ph[8][4], pl[8][4];
#pragma unroll
        for (int nt = 0; nt < 16; nt++) {
            float p0 = __expf(sacc[nt][0]);
            float p1 = __expf(sacc[nt][1]);
            float p2 = __expf(sacc[nt][2]);
            float p3 = __expf(sacc[nt][3]);
            ls0 += p0 + p1;
            ls1 += p2 + p3;
            unsigned short h0,l0,h1,l1,h2,l2,h3,l3;
            splitbf(p0,h0,l0); splitbf(p1,h1,l1);
            splitbf(p2,h2,l2); splitbf(p3,h3,l3);
            int kc = nt >> 1, o = (nt & 1) * 2;
            ph[kc][o]     = pk2(h0, h1);
            ph[kc][o + 1] = pk2(h2, h3);
            pl[kc][o]     = pk2(l0, l1);
            pl[kc][o + 1] = pk2(l2, l3);
        }

        // ---- O += Ph.Vh + Pl.Vh + Ph.Vl ----
#pragma unroll
        for (int ks = 0; ks < 8; ks++) {
            const int kb = ks * 32;
#pragma unroll
            for (int g = 0; g < 4; g++) {
                unsigned bfh[4], bfl[4];
                ldB(bfh, stb + 36864, 272, g * 16, kb, lane);
                mma_bf16(oacc[2*g],   ph[ks], bfh[0], bfh[1]);
                mma_bf16(oacc[2*g+1], ph[ks], bfh[2], bfh[3]);
                mma_bf16(oacc[2*g],   pl[ks], bfh[0], bfh[1]);
                mma_bf16(oacc[2*g+1], pl[ks], bfh[2], bfh[3]);
                ldB(bfl, stb + 54272, 272, g * 16, kb, lane);
                mma_bf16(oacc[2*g],   ph[ks], bfl[0], bfl[1]);
                mma_bf16(oacc[2*g+1], ph[ks], bfl[2], bfl[3]);
            }
        }
        __syncthreads();      // all reads done before this stage is refilled
    }

    // ---- rowsum: quad-reduce ----
    ls0 += __shfl_xor_sync(0xffffffffu, ls0, 1);
    ls0 += __shfl_xor_sync(0xffffffffu, ls0, 2);
    ls1 += __shfl_xor_sync(0xffffffffu, ls1, 1);
    ls1 += __shfl_xor_sync(0xffffffffu, ls1, 2);
    const float inv0 = 1.f / ls0, inv1 = 1.f / ls1;

    // ---- normalize + split write to concat ----
    const int r = m0 + (lane >> 2);
    const size_t base0 = ((size_t)b * SLEN + q0 + r) * DMODEL + h * KDIM;
    const size_t base1 = base0 + 8 * DMODEL;
#pragma unroll
    for (int nt = 0; nt < 8; nt++) {
        int col = nt * 8 + (lane & 3) * 2;
        float v0 = oacc[nt][0] * inv0, v1 = oacc[nt][1] * inv0;
        float v2 = oacc[nt][2] * inv1, v3 = oacc[nt][3] * inv1;
        unsigned short h0,l0,h1,l1,h2,l2,h3,l3;
        splitbf(v0,h0,l0); splitbf(v1,h1,l1);
        splitbf(v2,h2,l2); splitbf(v3,h3,l3);
        *(unsigned*)(g_ch + base0 + col) = pk2(h0, h1);
        *(unsigned*)(g_cl + base0 + col) = pk2(l0, l1);
        *(unsigned*)(g_ch + base1 + col) = pk2(h2, h3);
        *(unsigned*)(g_cl + base1 + col) = pk2(l2, l3);
    }
}

// ================= output projection (cp.async 2-stage) =================
// grid (64, 4), block 256. stage: A_H 0, A_L 18432, B_H 36864, B_L 55296
#define OSTG 73728
#define OUT_SMEM (2 * OSTG)     // 147456
__global__ __launch_bounds__(256, 1) void outproj_mma(float* __restrict__ out) {
    extern __shared__ char smc[];
    const unsigned sb = smem_u32(smc);
    const int tid = threadIdx.x, wid = tid >> 5, lane = tid & 31;
    const int wm = wid >> 1, wn = wid & 1;
    const int row0 = blockIdx.x * 128, n0 = blockIdx.y * 128;

    auto issue = [&](int c8) {
        const unsigned ob = sb + (c8 & 1) * OSTG;
        const int e0 = c8 * 64;
#pragma unroll
        for (int t = 0; t < 4; t++) {
            int idx = tid + t * 256, r = idx >> 3, q = idx & 7;
            size_t so = (size_t)(row0 + r) * 512 + e0 + q * 8;
            CP16(ob + r * 144 + q * 16, g_ch + so);
            CP16(ob + 18432 + r * 144 + q * 16, g_cl + so);
        }
#pragma unroll
        for (int t = 0; t < 4; t++) {
            int idx = tid + t * 256, r = idx >> 3, q = idx & 7;
            size_t so = (size_t)(n0 + r) * 512 + e0 + q * 8;
            CP16(ob + 36864 + r * 144 + q * 16, g_hkth + so);
            CP16(ob + 55296 + r * 144 + q * 16, g_hktl + so);
        }
    };

    float acc[2][8][4];
#pragma unroll
    for (int a = 0; a < 2; a++)
#pragma unroll
        for (int n = 0; n < 8; n++)
#pragma unroll
            for (int c = 0; c < 4; c++) acc[a][n][c] = 0.f;

    issue(0); CPCOMMIT();
    for (int c8 = 0; c8 < 8; c8++) {
        if (c8 < 7) { issue(c8 + 1); CPCOMMIT(); CPWAIT1(); } else { CPWAIT0(); }
        __syncthreads();
        const unsigned ob = sb + (c8 & 1) * OSTG;
#pragma unroll
        for (int ks = 0; ks < 4; ks++) {
            const int kb = ks * 32;
            unsigned ah0[4], ah1[4], al0[4], al1[4];
            ldA(ah0, ob, 144, wm * 32,      kb, lane);
            ldA(ah1, ob, 144, wm * 32 + 16, kb, lane);
            ldA(al0, ob + 18432, 144, wm * 32,      kb, lane);
            ldA(al1, ob + 18432, 144, wm * 32 + 16, kb, lane);
#pragma unroll
            for (int g = 0; g < 4; g++) {
                unsigned bh[4], bl[4];
                ldB(bh, ob + 36864, 144, wn * 64 + g * 16, kb, lane);
                ldB(bl, ob + 55296, 144, wn * 64 + g * 16, kb, lane);
                mma_bf16(acc[0][2*g],   ah0, bh[0], bh[1]);
                mma_bf16(acc[0][2*g+1], ah0, bh[2], bh[3]);
                mma_bf16(acc[1][2*g],   ah1, bh[0], bh[1]);
                mma_bf16(acc[1][2*g+1], ah1, bh[2], bh[3]);
                mma_bf16(acc[0][2*g],   ah0, bl[0], bl[1]);
                mma_bf16(acc[0][2*g+1], ah0, bl[2], bl[3]);
                mma_bf16(acc[1][2*g],   ah1, bl[0], bl[1]);
                mma_bf16(acc[1][2*g+1], ah1, bl[2], bl[3]);
                mma_bf16(acc[0][2*g],   al0, bh[0], bh[1]);
                mma_bf16(acc[0][2*g+1], al0, bh[2], bh[3]);
                mma_bf16(acc[1][2*g],   al1, bh[0], bh[1]);
                mma_bf16(acc[1][2*g+1], al1, bh[2], bh[3]);
            }
        }
        __syncthreads();
    }

#pragma unroll
    for (int mt = 0; mt < 2; mt++) {
        int r0 = row0 + wm * 32 + mt * 16 + (lane >> 2);
#pragma unroll
        for (int hf = 0; hf < 2; hf++) {
            size_t base = (size_t)(r0 + hf * 8) * DMODEL + n0;
#pragma unroll
            for (int nt = 0; nt < 8; nt++) {
                int col = wn * 64 + nt * 8 + (lane & 3) * 2;
                out[base + col]     = acc[mt][nt][hf * 2 + 0];
                out[base + col + 1] = acc[mt][nt][hf * 2 + 1];
            }
        }
    }
}

// =====================================================================
extern "C" void kernel_launch(void* const* d_in, const int* in_sizes, int n_in,
                              void* d_out, int out_size)
{
    const float* x    = (const float*)d_in[0];   // (4, 2048, 512)
    const float* kern = (const float*)d_in[1];   // (24, 512, 64)
    const float* hk   = (const float*)d_in[2];   // (512, 512)
    float* out = (float*)d_out;                  // (4, 2048, 512)

    cudaFuncSetAttribute(qkv_mma,     cudaFuncAttributeMaxDynamicSharedMemorySize, QKV_SMEM);
    cudaFuncSetAttribute(attn_mma,    cudaFuncAttributeMaxDynamicSharedMemorySize, ATT_SMEM);
    cudaFuncSetAttribute(outproj_mma, cudaFuncAttributeMaxDynamicSharedMemorySize, OUT_SMEM);

    const int n4x = BSROWS * DMODEL / 4;                     // 1048576
    convert_x<<<(n4x + 255) / 256, 256>>>(x, n4x);
    transpose_split<<<(24 * 64 * 64 + 255) / 256, 256>>>(kern, 0, 64, 24 * 64 * 64);
    transpose_split<<<(64 * 512 + 255) / 256, 256>>>(hk, 1, 512, 64 * 512);

    qkv_mma<<<dim3(BSROWS / 128, HNUM), 512, QKV_SMEM>>>();
    attn_mma<<<dim3(SLEN / 128, NBH), 256, ATT_SMEM>>>();
    outproj_mma<<<dim3(BSROWS / 128, DMODEL / 128), 256, OUT_SMEM>>>(out);
}

// round 9
// speedup vs baseline: 3.8358x; 1.3044x over previous
#include <cuda_runtime.h>
#include <cuda_bf16.h>
#include <cuda_fp16.h>

#define BDIM   4
#define SLEN   2048
#define DMODEL 512
#define HNUM   8
#define KDIM   64
#define BSROWS (BDIM * SLEN)   // 8192
#define NBH    (BDIM * HNUM)   // 32

// ---------------- scratch (static device globals) ----------------
__device__ __align__(16) unsigned short g_xh[BSROWS * DMODEL], g_xl[BSROWS * DMODEL];
__device__ __align__(16) unsigned short g_wth[24 * KDIM * DMODEL], g_wtl[24 * KDIM * DMODEL]; // [hj][n][d] bf16
__device__ __align__(16) unsigned short g_hkth[DMODEL * DMODEL];                              // [n][e] fp16
__device__ __align__(16) unsigned short g_qh[NBH * SLEN * KDIM], g_ql[NBH * SLEN * KDIM];     // [bh][s][d] bf16
__device__ __align__(16) unsigned short g_kh[NBH * SLEN * KDIM], g_kl[NBH * SLEN * KDIM];     // [bh][t][d] bf16
__device__ __align__(16) unsigned short g_vth[NBH * KDIM * SLEN];                             // [bh][d][t] fp16
__device__ __align__(16) unsigned short g_ch[BSROWS * DMODEL];                                // [row][e] fp16

// ---------------- helpers ----------------
__device__ __forceinline__ unsigned smem_u32(const void* p) {
    unsigned a;
    asm("{ .reg .u64 t; cvta.to.shared.u64 t, %1; cvt.u32.u64 %0, t; }" : "=r"(a) : "l"(p));
    return a;
}
#define CP16(dst, src) \
    asm volatile("cp.async.cg.shared.global [%0], [%1], 16;" :: "r"(dst), "l"(src))
#define CPCOMMIT() asm volatile("cp.async.commit_group;" ::: "memory")
#define CPWAIT0()  asm volatile("cp.async.wait_group 0;" ::: "memory")
#define CPWAIT1()  asm volatile("cp.async.wait_group 1;" ::: "memory")

__device__ __forceinline__ void ldsm4(unsigned* r, unsigned a) {
    asm volatile("ldmatrix.sync.aligned.m8n8.x4.shared.b16 {%0,%1,%2,%3}, [%4];"
        : "=r"(r[0]), "=r"(r[1]), "=r"(r[2]), "=r"(r[3]) : "r"(a));
}
// A operand m16 x k16 at (m0, kbyte), row-major smem, stride bytes
__device__ __forceinline__ void ldA(unsigned* r, unsigned base, int stride, int m0, int kb, int lane) {
    int row = m0 + (lane & 7) + ((lane >> 3) & 1) * 8;
    int col = kb + (lane >> 4) * 16;
    ldsm4(r, base + row * stride + col);
}
// B operand: two n8 tiles (n0, n0+8) x k16 at kbyte
__device__ __forceinline__ void ldB(unsigned* r, unsigned base, int stride, int n0, int kb, int lane) {
    int row = n0 + (lane & 7) + (lane >> 4) * 8;
    int col = kb + ((lane >> 3) & 1) * 16;
    ldsm4(r, base + row * stride + col);
}
__device__ __forceinline__ void mma_bf16(float* c, const unsigned* a, unsigned b0, unsigned b1) {
    asm volatile("mma.sync.aligned.m16n8k16.row.col.f32.bf16.bf16.f32 "
        "{%0,%1,%2,%3}, {%4,%5,%6,%7}, {%8,%9}, {%0,%1,%2,%3};"
        : "+f"(c[0]), "+f"(c[1]), "+f"(c[2]), "+f"(c[3])
        : "r"(a[0]), "r"(a[1]), "r"(a[2]), "r"(a[3]), "r"(b0), "r"(b1));
}
__device__ __forceinline__ void mma_fp16(float* c, const unsigned* a, unsigned b0, unsigned b1) {
    asm volatile("mma.sync.aligned.m16n8k16.row.col.f32.f16.f16.f32 "
        "{%0,%1,%2,%3}, {%4,%5,%6,%7}, {%8,%9}, {%0,%1,%2,%3};"
        : "+f"(c[0]), "+f"(c[1]), "+f"(c[2]), "+f"(c[3])
        : "r"(a[0]), "r"(a[1]), "r"(a[2]), "r"(a[3]), "r"(b0), "r"(b1));
}
__device__ __forceinline__ void splitbf(float x, unsigned short &h, unsigned short &l) {
    __nv_bfloat16 bh = __float2bfloat16(x);
    h = __bfloat16_as_ushort(bh);
    l = __bfloat16_as_ushort(__float2bfloat16(x - __bfloat162float(bh)));
}
__device__ __forceinline__ unsigned short f2h(float x) {
    __half v = __float2half_rn(x);
    return *(unsigned short*)&v;
}
__device__ __forceinline__ unsigned pk2(unsigned short a, unsigned short b) {
    return (unsigned)a | ((unsigned)b << 16);
}

// ================= convert kernels =================
__global__ void convert_x(const float* __restrict__ src, int n4) {
    int i = blockIdx.x * blockDim.x + threadIdx.x;
    if (i >= n4) return;
    float4 v = ((const float4*)src)[i];
    unsigned short h0,h1,h2,h3,l0,l1,l2,l3;
    splitbf(v.x,h0,l0); splitbf(v.y,h1,l1); splitbf(v.z,h2,l2); splitbf(v.w,h3,l3);
    ((uint2*)g_xh)[i] = make_uint2(pk2(h0,h1), pk2(h2,h3));
    ((uint2*)g_xl)[i] = make_uint2(pk2(l0,l1), pk2(l2,l3));
}
// w: [24][512][64] -> [24][64][512] bf16 split
__global__ void transpose_split_w(const float* __restrict__ src, int nwork) {
    int i = blockIdx.x * blockDim.x + threadIdx.x;
    if (i >= nwork) return;
    int n = i % 64, rest = i / 64;
    int d8 = rest & 63, mat = rest >> 6;
    int d0 = d8 * 8;
    unsigned short h[8], l[8];
#pragma unroll
    for (int j = 0; j < 8; j++)
        splitbf(src[(size_t)mat * 512 * 64 + (size_t)(d0 + j) * 64 + n], h[j], l[j]);
    size_t dst = (size_t)mat * 64 * 512 + (size_t)n * 512 + d0;
    *(uint4*)(g_wth + dst) = make_uint4(pk2(h[0],h[1]), pk2(h[2],h[3]), pk2(h[4],h[5]), pk2(h[6],h[7]));
    *(uint4*)(g_wtl + dst) = make_uint4(pk2(l[0],l[1]), pk2(l[2],l[3]), pk2(l[4],l[5]), pk2(l[6],l[7]));
}
// hk: [512][512] -> [512][512]^T fp16 single
__global__ void transpose_half_hk(const float* __restrict__ src, int nwork) {
    int i = blockIdx.x * blockDim.x + threadIdx.x;
    if (i >= nwork) return;
    int n = i % 512, d8 = i / 512;
    int d0 = d8 * 8;
    unsigned short h[8];
#pragma unroll
    for (int j = 0; j < 8; j++)
        h[j] = f2h(src[(size_t)(d0 + j) * 512 + n]);
    size_t dst = (size_t)n * 512 + d0;
    *(uint4*)(g_hkth + dst) = make_uint4(pk2(h[0],h[1]), pk2(h[2],h[3]), pk2(h[4],h[5]), pk2(h[6],h[7]));
}

// ================= QKV projection (fused, 512 thr, cp.async 2-stage) =================
// grid (64, 8). C[128x192] = x[128x512] . wt_head[192x512]^T, bf16 3-pass.
// stage layout (92160 B each): A_H 0, A_L 18432, B_H 36864, B_L 64512
#define QSTG 92160
#define QKV_SMEM (2 * QSTG)     // 184320
__global__ __launch_bounds__(512, 1) void qkv_mma() {
    extern __shared__ char smc[];
    const unsigned sb = smem_u32(smc);
    const int tid = threadIdx.x, wid = tid >> 5, lane = tid & 31;
    const int wm = wid >> 1, wn = wid & 1;
    const int h = blockIdx.y, row0 = blockIdx.x * 128;
    const int m0 = wm * 16, n0 = wn * 96;

    auto issue = [&](int c8) {
        const unsigned ab = sb + (c8 & 1) * QSTG;
        const int d0 = c8 * 64;
#pragma unroll
        for (int t = 0; t < 2; t++) {               // A: 128 rows x 8 x 16B (hi+lo)
            int idx = tid + t * 512, r = idx >> 3, q = idx & 7;
            size_t so = (size_t)(row0 + r) * 512 + d0 + q * 8;
            CP16(ab + r * 144 + q * 16, g_xh + so);
            CP16(ab + 18432 + r * 144 + q * 16, g_xl + so);
        }
#pragma unroll
        for (int t = 0; t < 3; t++) {               // B: 192 rows
            int idx = tid + t * 512, r = idx >> 3, q = idx & 7;
            size_t so = (size_t)(h * 192 + r) * 512 + d0 + q * 8;
            CP16(ab + 36864 + r * 144 + q * 16, g_wth + so);
            CP16(ab + 64512 + r * 144 + q * 16, g_wtl + so);
        }
    };

    float acc[12][4];
#pragma unroll
    for (int n = 0; n < 12; n++)
#pragma unroll
        for (int c = 0; c < 4; c++) acc[n][c] = 0.f;

    issue(0); CPCOMMIT();
    for (int c8 = 0; c8 < 8; c8++) {
        if (c8 < 7) { issue(c8 + 1); CPCOMMIT(); CPWAIT1(); } else { CPWAIT0(); }
        __syncthreads();
        const unsigned ab = sb + (c8 & 1) * QSTG;
#pragma unroll
        for (int ks = 0; ks < 4; ks++) {
            const int kb = ks * 32;
            unsigned ah[4], al[4];
            ldA(ah, ab, 144, m0, kb, lane);
            ldA(al, ab + 18432, 144, m0, kb, lane);
#pragma unroll
            for (int g = 0; g < 6; g++) {
                unsigned bh[4], bl[4];
                ldB(bh, ab + 36864, 144, n0 + g * 16, kb, lane);
                ldB(bl, ab + 64512, 144, n0 + g * 16, kb, lane);
                mma_bf16(acc[2*g],   ah, bh[0], bh[1]);
                mma_bf16(acc[2*g+1], ah, bh[2], bh[3]);
                mma_bf16(acc[2*g],   ah, bl[0], bl[1]);
                mma_bf16(acc[2*g+1], ah, bl[2], bl[3]);
                mma_bf16(acc[2*g],   al, bh[0], bh[1]);
                mma_bf16(acc[2*g+1], al, bh[2], bh[3]);
            }
        }
        __syncthreads();     // all reads done before this buffer is refilled
    }

    // writeout (stage-0 A region is free: last compute used stage 1)
#pragma unroll
    for (int half = 0; half < 2; half++) {
        int tl = m0 + half * 8 + (lane >> 2);       // local row
        int r = row0 + tl;
        int b = r >> 11, s = r & (SLEN - 1);
#pragma unroll
        for (int nt = 0; nt < 12; nt++) {
            int col = n0 + nt * 8 + (lane & 3) * 2;
            int j = col >> 6, cc = col & 63;
            float v0 = acc[nt][half * 2 + 0];
            float v1 = acc[nt][half * 2 + 1];
            if (j == 0) { v0 *= 0.125f; v1 *= 0.125f; }
            if (j < 2) {        // Q / K: bf16 split
                unsigned short h0,l0,h1,l1;
                splitbf(v0,h0,l0); splitbf(v1,h1,l1);
                unsigned short* dh = (j == 0) ? g_qh : g_kh;
                unsigned short* dl = (j == 0) ? g_ql : g_kl;
                size_t base = ((size_t)(b * HNUM + h) * SLEN + s) * KDIM + cc;
                *(unsigned*)(dh + base) = pk2(h0, h1);
                *(unsigned*)(dl + base) = pk2(l0, l1);
            } else {            // V: fp16 single, stage [d][t] into free stage-0 region
                *(unsigned short*)(smc + (cc    ) * 272 + tl * 2) = f2h(v0);
                *(unsigned short*)(smc + (cc + 1) * 272 + tl * 2) = f2h(v1);
            }
        }
    }
    __syncthreads();
    {
        const int b = row0 >> 11, s0 = row0 & (SLEN - 1);
        const size_t vbase = ((size_t)(b * HNUM + h) * KDIM) * SLEN;
#pragma unroll
        for (int t = 0; t < 2; t++) {
            int idx = tid + t * 512;
            if (idx < 1024) {
                int d = idx >> 4, q = idx & 15;
                size_t go = vbase + (size_t)d * SLEN + s0 + q * 8;
                *(uint4*)(g_vth + go) = *(const uint4*)(smc + d * 272 + q * 16);
            }
        }
    }
}

// ================= attention (S: bf16 3-pass; PV: fp16 1-pass) =================
// grid (16, 32), block 256, 1 CTA/SM. Warp w owns q-rows 16w..16w+15.
// smem: Q_H 0, Q_L 18432; stage s at 36864 + s*54272:
//   K_H +0, K_L +18432, V +36864 (fp16, 17408 B)
#define ASTG0 36864
#define ASTG  54272
#define ATT_SMEM (ASTG0 + 2 * ASTG)   // 145408
__global__ __launch_bounds__(256, 1) void attn_mma() {
    extern __shared__ char smc[];
    const unsigned sb = smem_u32(smc);
    const int tid = threadIdx.x, wid = tid >> 5, lane = tid & 31;
    const int m0 = wid * 16;
    const int bh = blockIdx.y, q0 = blockIdx.x * 128;
    const int b = bh >> 3, h = bh & 7;

    const size_t kbase = (size_t)bh * SLEN * KDIM;
    const size_t vbase = (size_t)bh * KDIM * SLEN;

    auto issue_kv = [&](int it) {
        const unsigned stb = sb + ASTG0 + (it & 1) * ASTG;
        const int t0 = it * 128;
#pragma unroll
        for (int t = 0; t < 4; t++) {                 // K tile [t][d] bf16 split
            int idx = tid + t * 256, r = idx >> 3, q = idx & 7;
            size_t so = kbase + (size_t)(t0 + r) * KDIM + q * 8;
            CP16(stb + r * 144 + q * 16, g_kh + so);
            CP16(stb + 18432 + r * 144 + q * 16, g_kl + so);
        }
#pragma unroll
        for (int t = 0; t < 4; t++) {                 // Vt tile [d][t] fp16
            int idx = tid + t * 256;
            if (idx < 1024) {
                int d = idx >> 4, q = idx & 15;
                size_t so = vbase + (size_t)d * SLEN + t0 + q * 8;
                CP16(stb + 36864 + d * 272 + q * 16, g_vth + so);
            }
        }
    };

    // prologue: Q + stage 0 in one group
    {
        const size_t qb = ((size_t)bh * SLEN + q0) * KDIM;
#pragma unroll
        for (int t = 0; t < 4; t++) {
            int idx = tid + t * 256, r = idx >> 3, q = idx & 7;
            size_t so = qb + (size_t)r * KDIM + q * 8;
            CP16(sb + r * 144 + q * 16, g_qh + so);
            CP16(sb + 18432 + r * 144 + q * 16, g_ql + so);
        }
        issue_kv(0); CPCOMMIT();
    }

    float oacc[8][4];
    float ls0 = 0.f, ls1 = 0.f;
#pragma unroll
    for (int n = 0; n < 8; n++)
#pragma unroll
        for (int c = 0; c < 4; c++) oacc[n][c] = 0.f;

    for (int it = 0; it < 16; it++) {
        if (it < 15) { issue_kv(it + 1); CPCOMMIT(); CPWAIT1(); } else { CPWAIT0(); }
        __syncthreads();
        const unsigned stb = sb + ASTG0 + (it & 1) * ASTG;

        // ---- S = Q K^T : fused bf16 3-pass ----
        float sacc[16][4];
#pragma unroll
        for (int n = 0; n < 16; n++)
#pragma unroll
            for (int c = 0; c < 4; c++) sacc[n][c] = 0.f;
#pragma unroll
        for (int ks = 0; ks < 4; ks++) {
            const int kb = ks * 32;
            unsigned aqh[4], aql[4];
            ldA(aqh, sb, 144, m0, kb, lane);
            ldA(aql, sb + 18432, 144, m0, kb, lane);
#pragma unroll
            for (int g = 0; g < 8; g++) {
                unsigned bkh[4], bkl[4];
                ldB(bkh, stb, 144, g * 16, kb, lane);
                ldB(bkl, stb + 18432, 144, g * 16, kb, lane);
                mma_bf16(sacc[2*g],   aqh, bkh[0], bkh[1]);
                mma_bf16(sacc[2*g+1], aqh, bkh[2], bkh[3]);
                mma_bf16(sacc[2*g],   aqh, bkl[0], bkl[1]);
                mma_bf16(sacc[2*g+1], aqh, bkl[2], bkl[3]);
                mma_bf16(sacc[2*g],   aql, bkh[0], bkh[1]);
                mma_bf16(sacc[2*g+1], aql, bkh[2], bkh[3]);
            }
        }

        // ---- p = exp(s); pack P as fp16 A-fragments; rowsum from ROUNDED p ----
        unsigned ph[8][4];
#pragma unroll
        for (int nt = 0; nt < 16; nt++) {
            float p0 = __expf(sacc[nt][0]);
            float p1 = __expf(sacc[nt][1]);
            float p2 = __expf(sacc[nt][2]);
            float p3 = __expf(sacc[nt][3]);
            __half2 ha = __floats2half2_rn(p0, p1);
            __half2 hb = __floats2half2_rn(p2, p3);
            float2 fa = __half22float2(ha);
            float2 fb = __half22float2(hb);
            ls0 += fa.x + fa.y;
            ls1 += fb.x + fb.y;
            int kc = nt >> 1, o = (nt & 1) * 2;
            ph[kc][o]     = *(unsigned*)&ha;
            ph[kc][o + 1] = *(unsigned*)&hb;
        }

        // ---- O += P V : fp16 single pass ----
#pragma unroll
        for (int ks = 0; ks < 8; ks++) {
            const int kb = ks * 32;
#pragma unroll
            for (int g = 0; g < 4; g++) {
                unsigned bf[4];
                ldB(bf, stb + 36864, 272, g * 16, kb, lane);
                mma_fp16(oacc[2*g],   ph[ks], bf[0], bf[1]);
                mma_fp16(oacc[2*g+1], ph[ks], bf[2], bf[3]);
            }
        }
        __syncthreads();      // all reads done before this stage is refilled
    }

    // ---- rowsum: quad-reduce ----
    ls0 += __shfl_xor_sync(0xffffffffu, ls0, 1);
    ls0 += __shfl_xor_sync(0xffffffffu, ls0, 2);
    ls1 += __shfl_xor_sync(0xffffffffu, ls1, 1);
    ls1 += __shfl_xor_sync(0xffffffffu, ls1, 2);
    const float inv0 = 1.f / ls0, inv1 = 1.f / ls1;

    // ---- normalize + fp16 write to concat ----
    const int r = m0 + (lane >> 2);
    const size_t base0 = ((size_t)b * SLEN + q0 + r) * DMODEL + h * KDIM;
    const size_t base1 = base0 + 8 * DMODEL;
#pragma unroll
    for (int nt = 0; nt < 8; nt++) {
        int col = nt * 8 + (lane & 3) * 2;
        *(unsigned*)(g_ch + base0 + col) = pk2(f2h(oacc[nt][0] * inv0), f2h(oacc[nt][1] * inv0));
        *(unsigned*)(g_ch + base1 + col) = pk2(f2h(oacc[nt][2] * inv1), f2h(oacc[nt][3] * inv1));
    }
}

// ================= output projection (fp16 1-pass, cp.async 2-stage) =================
// grid (64, 4), block 256. stage: A 0 (18432), B 18432 (18432)
#define OSTG 36864
#define OUT_SMEM (2 * OSTG)     // 73728
__global__ __launch_bounds__(256, 1) void outproj_mma(float* __restrict__ out) {
    extern __shared__ char smc[];
    const unsigned sb = smem_u32(smc);
    const int tid = threadIdx.x, wid = tid >> 5, lane = tid & 31;
    const int wm = wid >> 1, wn = wid & 1;
    const int row0 = blockIdx.x * 128, n0 = blockIdx.y * 128;

    auto issue = [&](int c8) {
        const unsigned ob = sb + (c8 & 1) * OSTG;
        const int e0 = c8 * 64;
#pragma unroll
        for (int t = 0; t < 4; t++) {
            int idx = tid + t * 256, r = idx >> 3, q = idx & 7;
            size_t soA = (size_t)(row0 + r) * 512 + e0 + q * 8;
            size_t soB = (size_t)(n0 + r) * 512 + e0 + q * 8;
            CP16(ob + r * 144 + q * 16, g_ch + soA);
            CP16(ob + 18432 + r * 144 + q * 16, g_hkth + soB);
        }
    };

    float acc[2][8][4];
#pragma unroll
    for (int a = 0; a < 2; a++)
#pragma unroll
        for (int n = 0; n < 8; n++)
#pragma unroll
            for (int c = 0; c < 4; c++) acc[a][n][c] = 0.f;

    issue(0); CPCOMMIT();
    for (int c8 = 0; c8 < 8; c8++) {
        if (c8 < 7) { issue(c8 + 1); CPCOMMIT(); CPWAIT1(); } else { CPWAIT0(); }
        __syncthreads();
        const unsigned ob = sb + (c8 & 1) * OSTG;
#pragma unroll
        for (int ks = 0; ks < 4; ks++) {
            const int kb = ks * 32;
            unsigned a0[4], a1[4];
            ldA(a0, ob, 144, wm * 32,      kb, lane);
            ldA(a1, ob, 144, wm * 32 + 16, kb, lane);
#pragma unroll
            for (int g = 0; g < 4; g++) {
                unsigned bf[4];
                ldB(bf, ob + 18432, 144, wn * 64 + g * 16, kb, lane);
                mma_fp16(acc[0][2*g],   a0, bf[0], bf[1]);
                mma_fp16(acc[0][2*g+1], a0, bf[2], bf[3]);
                mma_fp16(acc[1][2*g],   a1, bf[0], bf[1]);
                mma_fp16(acc[1][2*g+1], a1, bf[2], bf[3]);
            }
        }
        __syncthreads();
    }

#pragma unroll
    for (int mt = 0; mt < 2; mt++) {
        int r0 = row0 + wm * 32 + mt * 16 + (lane >> 2);
#pragma unroll
        for (int hf = 0; hf < 2; hf++) {
            size_t base = (size_t)(r0 + hf * 8) * DMODEL + n0;
#pragma unroll
            for (int nt = 0; nt < 8; nt++) {
                int col = wn * 64 + nt * 8 + (lane & 3) * 2;
                out[base + col]     = acc[mt][nt][hf * 2 + 0];
                out[base + col + 1] = acc[mt][nt][hf * 2 + 1];
            }
        }
    }
}

// =====================================================================
extern "C" void kernel_launch(void* const* d_in, const int* in_sizes, int n_in,
                              void* d_out, int out_size)
{
    const float* x    = (const float*)d_in[0];   // (4, 2048, 512)
    const float* kern = (const float*)d_in[1];   // (24, 512, 64)
    const float* hk   = (const float*)d_in[2];   // (512, 512)
    float* out = (float*)d_out;                  // (4, 2048, 512)

    cudaFuncSetAttribute(qkv_mma,     cudaFuncAttributeMaxDynamicSharedMemorySize, QKV_SMEM);
    cudaFuncSetAttribute(attn_mma,    cudaFuncAttributeMaxDynamicSharedMemorySize, ATT_SMEM);
    cudaFuncSetAttribute(outproj_mma, cudaFuncAttributeMaxDynamicSharedMemorySize, OUT_SMEM);

    const int n4x = BSROWS * DMODEL / 4;                     // 1048576
    convert_x<<<(n4x + 255) / 256, 256>>>(x, n4x);
    transpose_split_w<<<(24 * 64 * 64 + 255) / 256, 256>>>(kern, 24 * 64 * 64);
    transpose_half_hk<<<(64 * 512 + 255) / 256, 256>>>(hk, 64 * 512);

    qkv_mma<<<dim3(BSROWS / 128, HNUM), 512, QKV_SMEM>>>();
    attn_mma<<<dim3(SLEN / 128, NBH), 256, ATT_SMEM>>>();
    outproj_mma<<<dim3(BSROWS / 128, DMODEL / 128), 256, OUT_SMEM>>>(out);
}

// round 10
// speedup vs baseline: 6.4280x; 1.6758x over previous
#include <cuda_runtime.h>
#include <cuda_fp16.h>

#define BDIM   4
#define SLEN   2048
#define DMODEL 512
#define HNUM   8
#define KDIM   64
#define BSROWS (BDIM * SLEN)   // 8192
#define NBH    (BDIM * HNUM)   // 32

// ---------------- scratch (static device globals, all fp16-as-ushort) ----------------
__device__ __align__(16) unsigned short g_xf[BSROWS * DMODEL];          // x
__device__ __align__(16) unsigned short g_wtf[24 * KDIM * DMODEL];      // [hj][n][d]
__device__ __align__(16) unsigned short g_hktf[DMODEL * DMODEL];        // [n][e]
__device__ __align__(16) unsigned short g_qf[NBH * SLEN * KDIM];        // [bh][s][d] (pre-scaled 1/8)
__device__ __align__(16) unsigned short g_kf[NBH * SLEN * KDIM];        // [bh][t][d]
__device__ __align__(16) unsigned short g_vtf[NBH * KDIM * SLEN];       // [bh][d][t]
__device__ __align__(16) unsigned short g_cf[BSROWS * DMODEL];          // concat [row][e]

// ---------------- helpers ----------------
__device__ __forceinline__ unsigned smem_u32(const void* p) {
    unsigned a;
    asm("{ .reg .u64 t; cvta.to.shared.u64 t, %1; cvt.u32.u64 %0, t; }" : "=r"(a) : "l"(p));
    return a;
}
#define CP16(dst, src) \
    asm volatile("cp.async.cg.shared.global [%0], [%1], 16;" :: "r"(dst), "l"(src))
#define CPCOMMIT() asm volatile("cp.async.commit_group;" ::: "memory")
#define CPWAIT0()  asm volatile("cp.async.wait_group 0;" ::: "memory")
#define CPWAIT1()  asm volatile("cp.async.wait_group 1;" ::: "memory")

__device__ __forceinline__ void ldsm4(unsigned* r, unsigned a) {
    asm volatile("ldmatrix.sync.aligned.m8n8.x4.shared.b16 {%0,%1,%2,%3}, [%4];"
        : "=r"(r[0]), "=r"(r[1]), "=r"(r[2]), "=r"(r[3]) : "r"(a));
}
// A operand m16 x k16 at (m0, kbyte), row-major smem, stride bytes
__device__ __forceinline__ void ldA(unsigned* r, unsigned base, int stride, int m0, int kb, int lane) {
    int row = m0 + (lane & 7) + ((lane >> 3) & 1) * 8;
    int col = kb + (lane >> 4) * 16;
    ldsm4(r, base + row * stride + col);
}
// B operand: two n8 tiles (n0, n0+8) x k16 at kbyte
__device__ __forceinline__ void ldB(unsigned* r, unsigned base, int stride, int n0, int kb, int lane) {
    int row = n0 + (lane & 7) + (lane >> 4) * 8;
    int col = kb + ((lane >> 3) & 1) * 16;
    ldsm4(r, base + row * stride + col);
}
__device__ __forceinline__ void mma_fp16(float* c, const unsigned* a, unsigned b0, unsigned b1) {
    asm volatile("mma.sync.aligned.m16n8k16.row.col.f32.f16.f16.f32 "
        "{%0,%1,%2,%3}, {%4,%5,%6,%7}, {%8,%9}, {%0,%1,%2,%3};"
        : "+f"(c[0]), "+f"(c[1]), "+f"(c[2]), "+f"(c[3])
        : "r"(a[0]), "r"(a[1]), "r"(a[2]), "r"(a[3]), "r"(b0), "r"(b1));
}
__device__ __forceinline__ unsigned short f2h(float x) {
    __half v = __float2half_rn(x);
    return *(unsigned short*)&v;
}
__device__ __forceinline__ unsigned pk2(unsigned short a, unsigned short b) {
    return (unsigned)a | ((unsigned)b << 16);
}

// ================= convert kernels =================
__global__ void convert_x(const float* __restrict__ src, int n4) {
    int i = blockIdx.x * blockDim.x + threadIdx.x;
    if (i >= n4) return;
    float4 v = ((const float4*)src)[i];
    ((uint2*)g_xf)[i] = make_uint2(pk2(f2h(v.x), f2h(v.y)), pk2(f2h(v.z), f2h(v.w)));
}
// w: [24][512][64] -> [24][64][512] fp16
__global__ void transpose_w(const float* __restrict__ src, int nwork) {
    int i = blockIdx.x * blockDim.x + threadIdx.x;
    if (i >= nwork) return;
    int n = i % 64, rest = i / 64;
    int d8 = rest & 63, mat = rest >> 6;
    int d0 = d8 * 8;
    unsigned short h[8];
#pragma unroll
    for (int j = 0; j < 8; j++)
        h[j] = f2h(src[(size_t)mat * 512 * 64 + (size_t)(d0 + j) * 64 + n]);
    size_t dst = (size_t)mat * 64 * 512 + (size_t)n * 512 + d0;
    *(uint4*)(g_wtf + dst) = make_uint4(pk2(h[0],h[1]), pk2(h[2],h[3]), pk2(h[4],h[5]), pk2(h[6],h[7]));
}
// hk: [512][512] -> transposed fp16
__global__ void transpose_hk(const float* __restrict__ src, int nwork) {
    int i = blockIdx.x * blockDim.x + threadIdx.x;
    if (i >= nwork) return;
    int n = i % 512, d8 = i / 512;
    int d0 = d8 * 8;
    unsigned short h[8];
#pragma unroll
    for (int j = 0; j < 8; j++)
        h[j] = f2h(src[(size_t)(d0 + j) * 512 + n]);
    size_t dst = (size_t)n * 512 + d0;
    *(uint4*)(g_hktf + dst) = make_uint4(pk2(h[0],h[1]), pk2(h[2],h[3]), pk2(h[4],h[5]), pk2(h[6],h[7]));
}

// ================= QKV projection (fp16 1-pass, cp.async 2-stage) =================
// grid (64, 8), block 256. C[128x192] = x[128x512] . wt_head[192x512]^T.
// 8 warps as 4m x 2n: warp tile 32 x 96. cols: 0..63 q (x0.125), 64..127 k, 128..191 v.
// stage (46080 B): A 0 (18432 = 128x144), B 18432 (27648 = 192x144)
#define QSTG 46080
#define QKV_SMEM (2 * QSTG)     // 92160
__global__ __launch_bounds__(256, 1) void qkv_mma() {
    extern __shared__ char smc[];
    const unsigned sb = smem_u32(smc);
    const int tid = threadIdx.x, wid = tid >> 5, lane = tid & 31;
    const int wm = wid >> 1, wn = wid & 1;
    const int h = blockIdx.y, row0 = blockIdx.x * 128;
    const int m0 = wm * 32, n0 = wn * 96;

    auto issue = [&](int c8) {
        const unsigned ab = sb + (c8 & 1) * QSTG;
        const int d0 = c8 * 64;
#pragma unroll
        for (int t = 0; t < 4; t++) {               // A: 128 rows x 8 x 16B
            int idx = tid + t * 256, r = idx >> 3, q = idx & 7;
            CP16(ab + r * 144 + q * 16, g_xf + (size_t)(row0 + r) * 512 + d0 + q * 8);
        }
#pragma unroll
        for (int t = 0; t < 6; t++) {               // B: 192 rows
            int idx = tid + t * 256, r = idx >> 3, q = idx & 7;
            CP16(ab + 18432 + r * 144 + q * 16, g_wtf + (size_t)(h * 192 + r) * 512 + d0 + q * 8);
        }
    };

    float acc[2][12][4];
#pragma unroll
    for (int a = 0; a < 2; a++)
#pragma unroll
        for (int n = 0; n < 12; n++)
#pragma unroll
            for (int c = 0; c < 4; c++) acc[a][n][c] = 0.f;

    issue(0); CPCOMMIT();
    for (int c8 = 0; c8 < 8; c8++) {
        if (c8 < 7) { issue(c8 + 1); CPCOMMIT(); CPWAIT1(); } else { CPWAIT0(); }
        __syncthreads();
        const unsigned ab = sb + (c8 & 1) * QSTG;
#pragma unroll
        for (int ks = 0; ks < 4; ks++) {
            const int kb = ks * 32;
            unsigned a0[4], a1[4];
            ldA(a0, ab, 144, m0,      kb, lane);
            ldA(a1, ab, 144, m0 + 16, kb, lane);
#pragma unroll
            for (int g = 0; g < 6; g++) {
                unsigned bf[4];
                ldB(bf, ab + 18432, 144, n0 + g * 16, kb, lane);
                mma_fp16(acc[0][2*g],   a0, bf[0], bf[1]);
                mma_fp16(acc[0][2*g+1], a0, bf[2], bf[3]);
                mma_fp16(acc[1][2*g],   a1, bf[0], bf[1]);
                mma_fp16(acc[1][2*g+1], a1, bf[2], bf[3]);
            }
        }
        __syncthreads();
    }

    // writeout: q,k direct; v staged transposed in stage-0 region (free: last used stage 1)
#pragma unroll
    for (int mt = 0; mt < 2; mt++) {
#pragma unroll
        for (int half = 0; half < 2; half++) {
            int tl = m0 + mt * 16 + half * 8 + (lane >> 2);   // local row 0..127
            int r = row0 + tl;
            int b = r >> 11, s = r & (SLEN - 1);
#pragma unroll
            for (int nt = 0; nt < 12; nt++) {
                int col = n0 + nt * 8 + (lane & 3) * 2;
                int j = col >> 6, cc = col & 63;
                float v0 = acc[mt][nt][half * 2 + 0];
                float v1 = acc[mt][nt][half * 2 + 1];
                if (j == 0) { v0 *= 0.125f; v1 *= 0.125f; }
                if (j < 2) {
                    unsigned short* dst = (j == 0) ? g_qf : g_kf;
                    size_t base = ((size_t)(b * HNUM + h) * SLEN + s) * KDIM + cc;
                    *(unsigned*)(dst + base) = pk2(f2h(v0), f2h(v1));
                } else {   // V: [d][t] into stage 0
                    *(unsigned short*)(smc + (cc    ) * 272 + tl * 2) = f2h(v0);
                    *(unsigned short*)(smc + (cc + 1) * 272 + tl * 2) = f2h(v1);
                }
            }
        }
    }
    __syncthreads();
    {
        const int b = row0 >> 11, s0 = row0 & (SLEN - 1);
        const size_t vbase = ((size_t)(b * HNUM + h) * KDIM) * SLEN;
#pragma unroll
        for (int t = 0; t < 4; t++) {
            int idx = tid + t * 256, d = idx >> 4, q = idx & 15;
            *(uint4*)(g_vtf + vbase + (size_t)d * SLEN + s0 + q * 8) =
                *(const uint4*)(smc + d * 272 + q * 16);
        }
    }
}

// ================= attention (all fp16, 1-pass S and PV) =================
// grid (16, 32), block 256. Warp w owns q-rows 16w..16w+15, full 128-t width.
// smem: Q 0 (18432); stage s at 18432 + s*35840: K +0 (18432), V +18432 (17408)
#define ASTG0 18432
#define ASTG  35840
#define ATT_SMEM (ASTG0 + 2 * ASTG)   // 90112
__global__ __launch_bounds__(256, 1) void attn_mma() {
    extern __shared__ char smc[];
    const unsigned sb = smem_u32(smc);
    const int tid = threadIdx.x, wid = tid >> 5, lane = tid & 31;
    const int m0 = wid * 16;
    const int bh = blockIdx.y, q0 = blockIdx.x * 128;
    const int b = bh >> 3, h = bh & 7;

    const size_t kbase = (size_t)bh * SLEN * KDIM;
    const size_t vbase = (size_t)bh * KDIM * SLEN;

    auto issue_kv = [&](int it) {
        const unsigned stb = sb + ASTG0 + (it & 1) * ASTG;
        const int t0 = it * 128;
#pragma unroll
        for (int t = 0; t < 4; t++) {                 // K tile [t][d]
            int idx = tid + t * 256, r = idx >> 3, q = idx & 7;
            CP16(stb + r * 144 + q * 16, g_kf + kbase + (size_t)(t0 + r) * KDIM + q * 8);
        }
#pragma unroll
        for (int t = 0; t < 4; t++) {                 // Vt tile [d][t]
            int idx = tid + t * 256, d = idx >> 4, q = idx & 15;
            CP16(stb + 18432 + d * 272 + q * 16, g_vtf + vbase + (size_t)d * SLEN + t0 + q * 8);
        }
    };

    // prologue: Q + stage 0
    {
        const size_t qb = ((size_t)bh * SLEN + q0) * KDIM;
#pragma unroll
        for (int t = 0; t < 4; t++) {
            int idx = tid + t * 256, r = idx >> 3, q = idx & 7;
            CP16(sb + r * 144 + q * 16, g_qf + qb + (size_t)r * KDIM + q * 8);
        }
        issue_kv(0); CPCOMMIT();
    }

    float oacc[8][4];
    float ls0 = 0.f, ls1 = 0.f;
#pragma unroll
    for (int n = 0; n < 8; n++)
#pragma unroll
        for (int c = 0; c < 4; c++) oacc[n][c] = 0.f;

    for (int it = 0; it < 16; it++) {
        if (it < 15) { issue_kv(it + 1); CPCOMMIT(); CPWAIT1(); } else { CPWAIT0(); }
        __syncthreads();
        const unsigned stb = sb + ASTG0 + (it & 1) * ASTG;

        // ---- S = Q K^T : fp16 single pass ----
        float sacc[16][4];
#pragma unroll
        for (int n = 0; n < 16; n++)
#pragma unroll
            for (int c = 0; c < 4; c++) sacc[n][c] = 0.f;
#pragma unroll
        for (int ks = 0; ks < 4; ks++) {
            const int kb = ks * 32;
            unsigned aq[4];
            ldA(aq, sb, 144, m0, kb, lane);
#pragma unroll
            for (int g = 0; g < 8; g++) {
                unsigned bk[4];
                ldB(bk, stb, 144, g * 16, kb, lane);
                mma_fp16(sacc[2*g],   aq, bk[0], bk[1]);
                mma_fp16(sacc[2*g+1], aq, bk[2], bk[3]);
            }
        }

        // ---- p = exp(s); pack P as fp16 A-fragments; rowsum from ROUNDED p ----
        unsigned ph[8][4];
#pragma unroll
        for (int nt = 0; nt < 16; nt++) {
            float p0 = __expf(sacc[nt][0]);
            float p1 = __expf(sacc[nt][1]);
            float p2 = __expf(sacc[nt][2]);
            float p3 = __expf(sacc[nt][3]);
            __half2 ha = __floats2half2_rn(p0, p1);
            __half2 hb = __floats2half2_rn(p2, p3);
            float2 fa = __half22float2(ha);
            float2 fb = __half22float2(hb);
            ls0 += fa.x + fa.y;
            ls1 += fb.x + fb.y;
            int kc = nt >> 1, o = (nt & 1) * 2;
            ph[kc][o]     = *(unsigned*)&ha;
            ph[kc][o + 1] = *(unsigned*)&hb;
        }

        // ---- O += P V : fp16 single pass ----
#pragma unroll
        for (int ks = 0; ks < 8; ks++) {
            const int kb = ks * 32;
#pragma unroll
            for (int g = 0; g < 4; g++) {
                unsigned bf[4];
                ldB(bf, stb + 18432, 272, g * 16, kb, lane);
                mma_fp16(oacc[2*g],   ph[ks], bf[0], bf[1]);
                mma_fp16(oacc[2*g+1], ph[ks], bf[2], bf[3]);
            }
        }
        __syncthreads();
    }

    // ---- rowsum: quad-reduce ----
    ls0 += __shfl_xor_sync(0xffffffffu, ls0, 1);
    ls0 += __shfl_xor_sync(0xffffffffu, ls0, 2);
    ls1 += __shfl_xor_sync(0xffffffffu, ls1, 1);
    ls1 += __shfl_xor_sync(0xffffffffu, ls1, 2);
    const float inv0 = 1.f / ls0, inv1 = 1.f / ls1;

    // ---- normalize + fp16 write to concat ----
    const int r = m0 + (lane >> 2);
    const size_t base0 = ((size_t)b * SLEN + q0 + r) * DMODEL + h * KDIM;
    const size_t base1 = base0 + 8 * DMODEL;
#pragma unroll
    for (int nt = 0; nt < 8; nt++) {
        int col = nt * 8 + (lane & 3) * 2;
        *(unsigned*)(g_cf + base0 + col) = pk2(f2h(oacc[nt][0] * inv0), f2h(oacc[nt][1] * inv0));
        *(unsigned*)(g_cf + base1 + col) = pk2(f2h(oacc[nt][2] * inv1), f2h(oacc[nt][3] * inv1));
    }
}

// ================= output projection (fp16 1-pass, cp.async 2-stage) =================
// grid (64, 4), block 256. stage: A 0 (18432), B 18432 (18432)
#define OSTG 36864
#define OUT_SMEM (2 * OSTG)     // 73728
__global__ __launch_bounds__(256, 1) void outproj_mma(float* __restrict__ out) {
    extern __shared__ char smc[];
    const unsigned sb = smem_u32(smc);
    const int tid = threadIdx.x, wid = tid >> 5, lane = tid & 31;
    const int wm = wid >> 1, wn = wid & 1;
    const int row0 = blockIdx.x * 128, n0 = blockIdx.y * 128;

    auto issue = [&](int c8) {
        const unsigned ob = sb + (c8 & 1) * OSTG;
        const int e0 = c8 * 64;
#pragma unroll
        for (int t = 0; t < 4; t++) {
            int idx = tid + t * 256, r = idx >> 3, q = idx & 7;
            CP16(ob + r * 144 + q * 16, g_cf + (size_t)(row0 + r) * 512 + e0 + q * 8);
            CP16(ob + 18432 + r * 144 + q * 16, g_hktf + (size_t)(n0 + r) * 512 + e0 + q * 8);
        }
    };

    float acc[2][8][4];
#pragma unroll
    for (int a = 0; a < 2; a++)
#pragma unroll
        for (int n = 0; n < 8; n++)
#pragma unroll
            for (int c = 0; c < 4; c++) acc[a][n][c] = 0.f;

    issue(0); CPCOMMIT();
    for (int c8 = 0; c8 < 8; c8++) {
        if (c8 < 7) { issue(c8 + 1); CPCOMMIT(); CPWAIT1(); } else { CPWAIT0(); }
        __syncthreads();
        const unsigned ob = sb + (c8 & 1) * OSTG;
#pragma unroll
        for (int ks = 0; ks < 4; ks++) {
            const int kb = ks * 32;
            unsigned a0[4], a1[4];
            ldA(a0, ob, 144, wm * 32,      kb, lane);
            ldA(a1, ob, 144, wm * 32 + 16, kb, lane);
#pragma unroll
            for (int g = 0; g < 4; g++) {
                unsigned bf[4];
                ldB(bf, ob + 18432, 144, wn * 64 + g * 16, kb, lane);
                mma_fp16(acc[0][2*g],   a0, bf[0], bf[1]);
                mma_fp16(acc[0][2*g+1], a0, bf[2], bf[3]);
                mma_fp16(acc[1][2*g],   a1, bf[0], bf[1]);
                mma_fp16(acc[1][2*g+1], a1, bf[2], bf[3]);
            }
        }
        __syncthreads();
    }

#pragma unroll
    for (int mt = 0; mt < 2; mt++) {
        int r0 = row0 + wm * 32 + mt * 16 + (lane >> 2);
#pragma unroll
        for (int hf = 0; hf < 2; hf++) {
            size_t base = (size_t)(r0 + hf * 8) * DMODEL + n0;
#pragma unroll
            for (int nt = 0; nt < 8; nt++) {
                int col = wn * 64 + nt * 8 + (lane & 3) * 2;
                out[base + col]     = acc[mt][nt][hf * 2 + 0];
                out[base + col + 1] = acc[mt][nt][hf * 2 + 1];
            }
        }
    }
}

// =====================================================================
extern "C" void kernel_launch(void* const* d_in, const int* in_sizes, int n_in,
                              void* d_out, int out_size)
{
    const float* x    = (const float*)d_in[0];   // (4, 2048, 512)
    const float* kern = (const float*)d_in[1];   // (24, 512, 64)
    const float* hk   = (const float*)d_in[2];   // (512, 512)
    float* out = (float*)d_out;                  // (4, 2048, 512)

    cudaFuncSetAttribute(qkv_mma,     cudaFuncAttributeMaxDynamicSharedMemorySize, QKV_SMEM);
    cudaFuncSetAttribute(attn_mma,    cudaFuncAttributeMaxDynamicSharedMemorySize, ATT_SMEM);
    cudaFuncSetAttribute(outproj_mma, cudaFuncAttributeMaxDynamicSharedMemorySize, OUT_SMEM);

    const int n4x = BSROWS * DMODEL / 4;                     // 1048576
    convert_x<<<(n4x + 255) / 256, 256>>>(x, n4x);
    transpose_w<<<(24 * 64 * 64 + 255) / 256, 256>>>(kern, 24 * 64 * 64);
    transpose_hk<<<(64 * 512 + 255) / 256, 256>>>(hk, 64 * 512);

    qkv_mma<<<dim3(BSROWS / 128, HNUM), 256, QKV_SMEM>>>();
    attn_mma<<<dim3(SLEN / 128, NBH), 256, ATT_SMEM>>>();
    outproj_mma<<<dim3(BSROWS / 128, DMODEL / 128), 256, OUT_SMEM>>>(out);
}